// round 8
// baseline (speedup 1.0000x reference)
#include <cuda_runtime.h>
#include <cuda_bf16.h>
#include <cstdint>

// ---------------------------------------------------------------------------
// NaiveAttention on GB300. B=4, N=4096, C=1024 fp32.
// R7: all GEMM operands pre-split to bf16 hi/lo in GMEM (split hoisted out of
// the mainloop); tcgen05 mainloop is pure LDG/STS + MMA at the tensor floor.
// Dual-target build: sm_103a pass -> tcgen05; base pass -> SIMT fallback.
// ---------------------------------------------------------------------------

#if !defined(__CUDA_ARCH__)
#define USE_TC 1
#elif defined(__CUDA_ARCH_FEAT_SM103_ALL) || defined(__CUDA_ARCH_FEAT_SM100_ALL) || \
      defined(__CUDA_ARCH_FEAT_SM101_ALL) || defined(__CUDA_ARCH_SPECIFIC__) || \
      defined(__CUDA_ARCH_FAMILY_SPECIFIC__)
#define USE_TC 1
#else
#define USE_TC 0
#endif

#define DIMC 1024
#define NSEQ 4096
#define NB   4

typedef __nv_bfloat16 bf16;

// Scratch (device globals — no allocation allowed).
__device__ bf16  g_xh [16777216], g_xl [16777216];   // x hi/lo
__device__ bf16  g_wth[4194304],  g_wtl[4194304];    // WqT..WoT hi/lo
__device__ bf16  g_qh [16777216], g_ql [16777216];
__device__ bf16  g_kh [16777216], g_kl [16777216];
__device__ float g_v  [16777216];
__device__ bf16  g_vth[16777216], g_vtl[16777216];   // v^T hi/lo
__device__ float g_s  [67108864];                    // scores fp32
__device__ bf16  g_ah [67108864], g_al [67108864];   // attn hi/lo
__device__ bf16  g_aoh[16777216], g_aol[16777216];   // attn@v hi/lo

#define KT 64
#define IDESC 0x8200490u   // f32 accum, bf16 x bf16, M=128, N=128
#define BUF_BYTES 65536    // Ahi(16K) Alo(16K) Bhi(16K) Blo(16K)
#define SMEM_BYTES (2048 + 2 * BUF_BYTES)

// ---- bf16 pack helpers (legal on base target too) -------------------------
__device__ __forceinline__ uint32_t pack_bf16(float lo, float hi) {
    uint32_t r;
    asm("cvt.rn.satfinite.bf16x2.f32 %0, %1, %2;" : "=r"(r) : "f"(hi), "f"(lo));
    return r;
}
__device__ __forceinline__ float bf16_rn_f32(float x) {
    uint32_t r;
    asm("cvt.rn.satfinite.bf16x2.f32 %0, %1, %1;" : "=r"(r) : "f"(x));
    return __uint_as_float(r << 16);
}

#if USE_TC
// ---------------------------------------------------------------------------
// sm_103a-only PTX helpers
// ---------------------------------------------------------------------------
__device__ __forceinline__ uint32_t smem_u32(const void* p) {
    uint32_t a;
    asm("{ .reg .u64 t; cvta.to.shared.u64 t, %1; cvt.u32.u64 %0, t; }"
        : "=r"(a) : "l"(p));
    return a;
}

#define MBAR_INIT(addr, cnt) \
    asm volatile("mbarrier.init.shared.b64 [%0], %1;" :: "r"(addr), "r"(cnt) : "memory")

#define MBAR_WAIT(addr, ph) do {                                              \
    uint32_t _m = (addr); uint32_t _p = (ph); uint32_t _done;                 \
    asm volatile("{\n\t.reg .pred p;\n\t"                                     \
        "mbarrier.try_wait.parity.acquire.cta.shared::cta.b64 p, [%1], %2;\n\t" \
        "selp.b32 %0, 1, 0, p;\n\t}"                                          \
        : "=r"(_done) : "r"(_m), "r"(_p) : "memory");                         \
    if (!_done) {                                                             \
        asm volatile("{\n\t.reg .pred P1;\n\t"                                \
            "WL_%=:\n\t"                                                      \
            "mbarrier.try_wait.parity.acquire.cta.shared::cta.b64 P1, [%0], %1, 0x989680;\n\t" \
            "@P1 bra.uni WD_%=;\n\t"                                          \
            "bra.uni WL_%=;\n\t"                                              \
            "WD_%=:\n\t}"                                                     \
            :: "r"(_m), "r"(_p) : "memory");                                  \
    }                                                                         \
} while (0)

#define TC_ALLOC(sm, n)   asm volatile("tcgen05.alloc.cta_group::1.sync.aligned.shared::cta.b32 [%0], %1;" :: "r"(sm), "r"(n) : "memory")
#define TC_DEALLOC(t, n)  asm volatile("tcgen05.dealloc.cta_group::1.sync.aligned.b32 %0, %1;" :: "r"(t), "r"(n))
#define TC_RELINQ()       asm volatile("tcgen05.relinquish_alloc_permit.cta_group::1.sync.aligned;")
#define TC_COMMIT(mb)     asm volatile("tcgen05.commit.cta_group::1.mbarrier::arrive::one.shared::cluster.b64 [%0];" :: "r"(mb) : "memory")
#define TC_FENCE_AFTER()  asm volatile("tcgen05.fence::after_thread_sync;" ::: "memory")
#define TC_FENCE_BEFORE() asm volatile("tcgen05.fence::before_thread_sync;" ::: "memory")
#define TC_WAIT_LD()      asm volatile("tcgen05.wait::ld.sync.aligned;" ::: "memory")
#define FENCE_ASYNC()     asm volatile("fence.proxy.async.shared::cta;" ::: "memory")

#define TC_LD_X32(r, a) \
    asm volatile("tcgen05.ld.sync.aligned.32x32b.x32.b32 " \
        "{%0, %1, %2, %3, %4, %5, %6, %7, %8, %9, %10, %11, %12, %13, %14, %15, " \
        " %16, %17, %18, %19, %20, %21, %22, %23, %24, %25, %26, %27, %28, %29, %30, %31}, [%32];" \
        : "=r"((r)[0]), "=r"((r)[1]), "=r"((r)[2]), "=r"((r)[3]), \
          "=r"((r)[4]), "=r"((r)[5]), "=r"((r)[6]), "=r"((r)[7]), \
          "=r"((r)[8]), "=r"((r)[9]), "=r"((r)[10]), "=r"((r)[11]), \
          "=r"((r)[12]), "=r"((r)[13]), "=r"((r)[14]), "=r"((r)[15]), \
          "=r"((r)[16]), "=r"((r)[17]), "=r"((r)[18]), "=r"((r)[19]), \
          "=r"((r)[20]), "=r"((r)[21]), "=r"((r)[22]), "=r"((r)[23]), \
          "=r"((r)[24]), "=r"((r)[25]), "=r"((r)[26]), "=r"((r)[27]), \
          "=r"((r)[28]), "=r"((r)[29]), "=r"((r)[30]), "=r"((r)[31]) \
        : "r"(a))

__device__ __forceinline__ void mma_f16_ss(uint32_t d, uint64_t a, uint64_t b,
                                           uint32_t idesc, uint32_t en) {
    asm volatile("{\n\t.reg .pred p;\n\tsetp.ne.u32 p, %4, 0;\n\t"
        "tcgen05.mma.cta_group::1.kind::f16 [%0], %1, %2, %3, {%5, %5, %5, %5}, p;\n\t}"
        :: "r"(d), "l"(a), "l"(b), "r"(idesc), "r"(en), "r"(0u) : "memory");
}

__device__ __forceinline__ uint64_t mk_desc(uint32_t addr) {
    const uint64_t base = (uint64_t(2) << 61) | (uint64_t(1) << 46)
                        | (uint64_t(64) << 32) | (uint64_t(1) << 16);
    return base | ((uint64_t)(addr >> 4) & 0x3FFF);
}
#endif  // USE_TC

// ---------------------------------------------------------------------------
// GEMM:  C[z] = (Ahi+Alo)[z] @ (Bhi+Blo)[z]^T (+ bias), 3-product split.
//   A*: [M,K] bf16 K-major, B*: [N,K] bf16 K-major.
//   OUTM=0: write Cf fp32 [M,N].  OUTM=1: write Chi/Clo bf16 hi/lo pair.
//   128x128 CTA tile, 256 threads. M,N % 128 == 0, K % 64 == 0.
// ---------------------------------------------------------------------------
template <int OUTM, bool HAS_BIAS>
__global__ __launch_bounds__(256, 1)
void tc_gemm2(const bf16* __restrict__ Ahi, const bf16* __restrict__ Alo,
              const bf16* __restrict__ Bhi, const bf16* __restrict__ Blo,
              const float* __restrict__ bias,
              float* __restrict__ Cf, bf16* __restrict__ Chi, bf16* __restrict__ Clo,
              int M, int N, int K,
              long long sA, long long sB, long long sC)
{
    extern __shared__ char smem[];

    Ahi += (long long)blockIdx.z * sA;  Alo += (long long)blockIdx.z * sA;
    Bhi += (long long)blockIdx.z * sB;  Blo += (long long)blockIdx.z * sB;

    const int tid = threadIdx.x;
    const int m0  = blockIdx.y * 128;
    const int n0  = blockIdx.x * 128;

#if USE_TC
    const uint32_t sb    = smem_u32(smem);
    const uint32_t tiles = (sb + 32 + 1023) & ~1023u;
    char* tilesg = smem + (tiles - sb);
    const uint32_t mbar0 = sb;
    const uint32_t mbar1 = sb + 8;
    const uint32_t tptr  = sb + 16;

    if (tid < 32) TC_ALLOC(tptr, 128);
    if (tid == 0) { MBAR_INIT(mbar0, 1); MBAR_INIT(mbar1, 1); }
    __syncthreads();
    uint32_t tmem;
    asm volatile("ld.shared.b32 %0, [%1];" : "=r"(tmem) : "r"(tptr));

    const int nk = K / KT;
    int ph0 = 0, ph1 = 0;

    // loader geometry: thread -> (row, 64B half-row), 4x 16B chunks
    const int lrow  = tid >> 1;
    const int lhalf = tid & 1;

    for (int t = 0; t < nk; t++) {
        const int buf = t & 1;
        char* bbg = tilesg + buf * BUF_BYTES;

        if (t >= 2) {
            if (buf == 0) { MBAR_WAIT(mbar0, ph0); ph0 ^= 1; }
            else          { MBAR_WAIT(mbar1, ph1); ph1 ^= 1; }
        }

        // ---- copy 4 bf16 tiles (no conversion math in the loop) ----
        {
            const bf16* srcs[4] = {
                Ahi + (long long)m0 * K + t * KT,
                Alo + (long long)m0 * K + t * KT,
                Bhi + (long long)n0 * K + t * KT,
                Blo + (long long)n0 * K + t * KT };
            #pragma unroll
            for (int r = 0; r < 4; r++) {
                const bf16* p = srcs[r] + (long long)lrow * K + lhalf * 32;
                char* dst = bbg + r * 16384;
                #pragma unroll
                for (int j = 0; j < 4; j++) {
                    uint4 vv = *reinterpret_cast<const uint4*>(p + j * 8);
                    uint32_t off = (uint32_t)(lrow * 128 + lhalf * 64 + j * 16);
                    uint32_t sw  = off ^ ((off >> 3) & 0x70);
                    *reinterpret_cast<uint4*>(dst + sw) = vv;
                }
            }
        }
        FENCE_ASYNC();
        __syncthreads();

        // ---- 12 MMAs (3 splits x 4 K-steps of 16) ----
        if (tid == 0) {
            const uint32_t bb = tiles + buf * BUF_BYTES;
            uint64_t ah = mk_desc(bb);
            uint64_t al = mk_desc(bb + 16384);
            uint64_t bh = mk_desc(bb + 32768);
            uint64_t bl = mk_desc(bb + 49152);
            #pragma unroll
            for (int kc = 0; kc < 4; kc++)
                mma_f16_ss(tmem, ah + kc * 2, bh + kc * 2, IDESC, (t | kc) != 0);
            #pragma unroll
            for (int kc = 0; kc < 4; kc++)
                mma_f16_ss(tmem, ah + kc * 2, bl + kc * 2, IDESC, 1);
            #pragma unroll
            for (int kc = 0; kc < 4; kc++)
                mma_f16_ss(tmem, al + kc * 2, bh + kc * 2, IDESC, 1);
            TC_COMMIT(buf == 0 ? mbar0 : mbar1);
        }
    }

    if (((nk - 1) & 1) == 0) { MBAR_WAIT(mbar0, ph0); }
    else                     { MBAR_WAIT(mbar1, ph1); }
    TC_FENCE_AFTER();

    if (HAS_BIAS) {
        if (tid < 128) ((float*)tilesg)[tid] = bias[n0 + tid];
        __syncthreads();
    }

    if (tid < 128) {
        uint32_t d[128];
        TC_LD_X32(d +  0, tmem +  0);
        TC_LD_X32(d + 32, tmem + 32);
        TC_LD_X32(d + 64, tmem + 64);
        TC_LD_X32(d + 96, tmem + 96);
        TC_WAIT_LD();
        TC_FENCE_BEFORE();
        const int row = m0 + tid;
        const float* bsm = (const float*)tilesg;

        if (OUTM == 0) {
            float* cp = Cf + (long long)blockIdx.z * sC + (long long)row * N + n0;
            #pragma unroll
            for (int c = 0; c < 128; c += 4) {
                float4 o;
                o.x = __uint_as_float(d[c + 0]);
                o.y = __uint_as_float(d[c + 1]);
                o.z = __uint_as_float(d[c + 2]);
                o.w = __uint_as_float(d[c + 3]);
                if (HAS_BIAS) {
                    o.x += bsm[c + 0]; o.y += bsm[c + 1];
                    o.z += bsm[c + 2]; o.w += bsm[c + 3];
                }
                *reinterpret_cast<float4*>(cp + c) = o;
            }
        } else {
            const long long rb = (long long)blockIdx.z * sC + (long long)row * N + n0;
            #pragma unroll
            for (int c = 0; c < 128; c += 8) {
                float v[8];
                #pragma unroll
                for (int j = 0; j < 8; j++) {
                    v[j] = __uint_as_float(d[c + j]);
                    if (HAS_BIAS) v[j] += bsm[c + j];
                }
                uint4 hw, lw;
                hw.x = pack_bf16(v[0], v[1]); hw.y = pack_bf16(v[2], v[3]);
                hw.z = pack_bf16(v[4], v[5]); hw.w = pack_bf16(v[6], v[7]);
                float l[8];
                #pragma unroll
                for (int j = 0; j < 8; j++) l[j] = v[j] - bf16_rn_f32(v[j]);
                lw.x = pack_bf16(l[0], l[1]); lw.y = pack_bf16(l[2], l[3]);
                lw.z = pack_bf16(l[4], l[5]); lw.w = pack_bf16(l[6], l[7]);
                *reinterpret_cast<uint4*>(Chi + rb + c) = hw;
                *reinterpret_cast<uint4*>(Clo + rb + c) = lw;
            }
        }
    }

    __syncthreads();
    if (tid == 0) {
        asm volatile("mbarrier.inval.shared.b64 [%0];" :: "r"(mbar0) : "memory");
        asm volatile("mbarrier.inval.shared.b64 [%0];" :: "r"(mbar1) : "memory");
    }
    __syncthreads();
    if (tid < 32) { TC_RELINQ(); TC_DEALLOC(tmem, 128); }

#else
    // ================= SIMT fallback (base target; never selected) =========
    float (*As)[128] = reinterpret_cast<float (*)[128]>(smem);
    float (*Bs)[128] = reinterpret_cast<float (*)[128]>(smem + 4096);

    const int ty = tid >> 4, tx = tid & 15;
    const int aRow = tid >> 1, aCol = (tid & 1) * 4;
    float acc[8][8] = {};

    for (int k0 = 0; k0 < K; k0 += 8) {
        #pragma unroll
        for (int e = 0; e < 4; e++) {
            long long ia = (long long)(m0 + aRow) * K + k0 + aCol + e;
            As[aCol + e][aRow] = __bfloat162float(Ahi[ia]) + __bfloat162float(Alo[ia]);
            long long ib = (long long)(n0 + aRow) * K + k0 + aCol + e;
            Bs[aCol + e][aRow] = __bfloat162float(Bhi[ib]) + __bfloat162float(Blo[ib]);
        }
        __syncthreads();
        #pragma unroll
        for (int kk = 0; kk < 8; kk++) {
            float ra[8], rb[8];
            #pragma unroll
            for (int i = 0; i < 8; i++) ra[i] = As[kk][ty * 8 + i];
            #pragma unroll
            for (int j = 0; j < 8; j++) rb[j] = Bs[kk][tx * 8 + j];
            #pragma unroll
            for (int i = 0; i < 8; i++)
                #pragma unroll
                for (int j = 0; j < 8; j++)
                    acc[i][j] = fmaf(ra[i], rb[j], acc[i][j]);
        }
        __syncthreads();
    }
    #pragma unroll
    for (int i = 0; i < 8; i++) {
        const int row = m0 + ty * 8 + i;
        #pragma unroll
        for (int j = 0; j < 8; j++) {
            const int col = n0 + tx * 8 + j;
            float val = acc[i][j] + (HAS_BIAS ? bias[col] : 0.f);
            long long o = (long long)blockIdx.z * sC + (long long)row * N + col;
            if (OUTM == 0) {
                Cf[o] = val;
            } else {
                float h = bf16_rn_f32(val);
                Chi[o] = __float2bfloat16(val);
                Clo[o] = __float2bfloat16(val - h);
            }
        }
    }
#endif
}

// ---------------------------------------------------------------------------
// Elementwise fp32 -> bf16 hi/lo split (n4 = count of float4 groups)
// ---------------------------------------------------------------------------
__global__ __launch_bounds__(256)
void conv_k(const float* __restrict__ in, bf16* __restrict__ oh,
            bf16* __restrict__ ol, long long n4)
{
    long long idx = (long long)blockIdx.x * blockDim.x + threadIdx.x;
    if (idx >= n4) return;
    float4 v = reinterpret_cast<const float4*>(in)[idx];
    uint2 hw, lw;
    hw.x = pack_bf16(v.x, v.y); hw.y = pack_bf16(v.z, v.w);
    lw.x = pack_bf16(v.x - bf16_rn_f32(v.x), v.y - bf16_rn_f32(v.y));
    lw.y = pack_bf16(v.z - bf16_rn_f32(v.z), v.w - bf16_rn_f32(v.w));
    reinterpret_cast<uint2*>(oh)[idx] = hw;
    reinterpret_cast<uint2*>(ol)[idx] = lw;
}

// ---------------------------------------------------------------------------
// 32x32 tiled transpose fp32 -> bf16 hi/lo:  out[c][r] = split(in[r][c])
// ---------------------------------------------------------------------------
__global__ __launch_bounds__(256)
void transpose_conv_k(const float* __restrict__ in,
                      bf16* __restrict__ oh, bf16* __restrict__ ol,
                      int R, int Cc, long long sIn, long long sOut)
{
    __shared__ float t[32][33];
    in += (long long)blockIdx.z * sIn;
    const long long ob = (long long)blockIdx.z * sOut;
    const int r0 = blockIdx.y * 32, c0 = blockIdx.x * 32;
    const int tx = threadIdx.x & 31, ty = threadIdx.x >> 5;
    #pragma unroll
    for (int i = 0; i < 32; i += 8)
        t[ty + i][tx] = in[(long long)(r0 + ty + i) * Cc + c0 + tx];
    __syncthreads();
    #pragma unroll
    for (int i = 0; i < 32; i += 8) {
        float v = t[tx][ty + i];
        float h = bf16_rn_f32(v);
        long long o = ob + (long long)(c0 + ty + i) * R + r0 + tx;
        oh[o] = __float2bfloat16(v);
        ol[o] = __float2bfloat16(v - h);
    }
}

// ---------------------------------------------------------------------------
// Row softmax (rows of 4096, scale folded), writes attn as bf16 hi/lo.
// Thread t owns 16 consecutive elements.
// ---------------------------------------------------------------------------
__global__ __launch_bounds__(256)
void softmax2_k(const float* __restrict__ S, bf16* __restrict__ AH,
                bf16* __restrict__ AL, float scale)
{
    const float* row = S + (long long)blockIdx.x * 4096;
    const long long ob = (long long)blockIdx.x * 4096;
    const int t = threadIdx.x;
    const int base = t * 16;
    __shared__ float red[256];

    float vals[16];
    float m = -1e30f;
    #pragma unroll
    for (int i = 0; i < 4; i++) {
        float4 v = reinterpret_cast<const float4*>(row + base)[i];
        vals[i * 4 + 0] = v.x; vals[i * 4 + 1] = v.y;
        vals[i * 4 + 2] = v.z; vals[i * 4 + 3] = v.w;
    }
    #pragma unroll
    for (int i = 0; i < 16; i++) m = fmaxf(m, vals[i]);
    red[t] = m;
    __syncthreads();
    #pragma unroll
    for (int s = 128; s > 0; s >>= 1) {
        if (t < s) red[t] = fmaxf(red[t], red[t + s]);
        __syncthreads();
    }
    m = red[0];
    __syncthreads();

    float sum = 0.f;
    #pragma unroll
    for (int i = 0; i < 16; i++) {
        vals[i] = __expf(scale * (vals[i] - m));
        sum += vals[i];
    }
    red[t] = sum;
    __syncthreads();
    #pragma unroll
    for (int s = 128; s > 0; s >>= 1) {
        if (t < s) red[t] += red[t + s];
        __syncthreads();
    }
    const float inv = 1.0f / red[0];

    uint4 hw[2], lw[2];
    #pragma unroll
    for (int g = 0; g < 2; g++) {
        float v[8], l[8];
        #pragma unroll
        for (int j = 0; j < 8; j++) {
            v[j] = vals[g * 8 + j] * inv;
            l[j] = v[j] - bf16_rn_f32(v[j]);
        }
        hw[g].x = pack_bf16(v[0], v[1]); hw[g].y = pack_bf16(v[2], v[3]);
        hw[g].z = pack_bf16(v[4], v[5]); hw[g].w = pack_bf16(v[6], v[7]);
        lw[g].x = pack_bf16(l[0], l[1]); lw[g].y = pack_bf16(l[2], l[3]);
        lw[g].z = pack_bf16(l[4], l[5]); lw[g].w = pack_bf16(l[6], l[7]);
    }
    reinterpret_cast<uint4*>(AH + ob + base)[0] = hw[0];
    reinterpret_cast<uint4*>(AH + ob + base)[1] = hw[1];
    reinterpret_cast<uint4*>(AL + ob + base)[0] = lw[0];
    reinterpret_cast<uint4*>(AL + ob + base)[1] = lw[1];
}

// ---------------------------------------------------------------------------
extern "C" void kernel_launch(void* const* d_in, const int* in_sizes, int n_in,
                              void* d_out, int out_size)
{
    const float* x  = (const float*)d_in[0];
    const float* Wq = (const float*)d_in[1];
    const float* bq = (const float*)d_in[2];
    const float* Wk = (const float*)d_in[3];
    const float* bk = (const float*)d_in[4];
    const float* Wv = (const float*)d_in[5];
    const float* bv = (const float*)d_in[6];
    const float* Wo = (const float*)d_in[7];
    const float* bo = (const float*)d_in[8];
    float* out = (float*)d_out;

    const int M = NB * NSEQ;                 // 16384
    const float scale = 0.03125f;

    bf16 *xh, *xl, *wth, *wtl, *qh, *ql, *kh, *kl, *vth, *vtl, *ah, *al, *aoh, *aol;
    float *v, *s;
    cudaGetSymbolAddress((void**)&xh,  g_xh);  cudaGetSymbolAddress((void**)&xl,  g_xl);
    cudaGetSymbolAddress((void**)&wth, g_wth); cudaGetSymbolAddress((void**)&wtl, g_wtl);
    cudaGetSymbolAddress((void**)&qh,  g_qh);  cudaGetSymbolAddress((void**)&ql,  g_ql);
    cudaGetSymbolAddress((void**)&kh,  g_kh);  cudaGetSymbolAddress((void**)&kl,  g_kl);
    cudaGetSymbolAddress((void**)&v,   g_v);
    cudaGetSymbolAddress((void**)&vth, g_vth); cudaGetSymbolAddress((void**)&vtl, g_vtl);
    cudaGetSymbolAddress((void**)&s,   g_s);
    cudaGetSymbolAddress((void**)&ah,  g_ah);  cudaGetSymbolAddress((void**)&al,  g_al);
    cudaGetSymbolAddress((void**)&aoh, g_aoh); cudaGetSymbolAddress((void**)&aol, g_aol);

    cudaFuncSetAttribute((const void*)tc_gemm2<0, true>,  cudaFuncAttributeMaxDynamicSharedMemorySize, SMEM_BYTES);
    cudaFuncSetAttribute((const void*)tc_gemm2<0, false>, cudaFuncAttributeMaxDynamicSharedMemorySize, SMEM_BYTES);
    cudaFuncSetAttribute((const void*)tc_gemm2<1, true>,  cudaFuncAttributeMaxDynamicSharedMemorySize, SMEM_BYTES);
    cudaFuncSetAttribute((const void*)tc_gemm2<1, false>, cudaFuncAttributeMaxDynamicSharedMemorySize, SMEM_BYTES);

    const long long qkv = (long long)NSEQ * DIMC;
    const long long ss  = (long long)NSEQ * NSEQ;

    dim3 b256(256);

    // 1) split x -> xh/xl  (16M elems = 4M float4s)
    conv_k<<<16384, b256>>>(x, xh, xl, 4194304);

    // 2) transpose+split weights
    {
        dim3 g(32, 32, 1);
        transpose_conv_k<<<g, b256>>>(Wq, wth + 0*1048576, wtl + 0*1048576, DIMC, DIMC, 0, 0);
        transpose_conv_k<<<g, b256>>>(Wk, wth + 1*1048576, wtl + 1*1048576, DIMC, DIMC, 0, 0);
        transpose_conv_k<<<g, b256>>>(Wv, wth + 2*1048576, wtl + 2*1048576, DIMC, DIMC, 0, 0);
        transpose_conv_k<<<g, b256>>>(Wo, wth + 3*1048576, wtl + 3*1048576, DIMC, DIMC, 0, 0);
    }

    // 3) q,k (bf16 pair out) and v (fp32 out) projections
    {
        dim3 g(DIMC / 128, M / 128, 1);
        tc_gemm2<1, true><<<g, b256, SMEM_BYTES>>>(xh, xl, wth + 0*1048576, wtl + 0*1048576,
                                                   bq, nullptr, qh, ql, M, DIMC, DIMC, 0, 0, 0);
        tc_gemm2<1, true><<<g, b256, SMEM_BYTES>>>(xh, xl, wth + 1*1048576, wtl + 1*1048576,
                                                   bk, nullptr, kh, kl, M, DIMC, DIMC, 0, 0, 0);
        tc_gemm2<0, true><<<g, b256, SMEM_BYTES>>>(xh, xl, wth + 2*1048576, wtl + 2*1048576,
                                                   bv, v, nullptr, nullptr, M, DIMC, DIMC, 0, 0, 0);
    }

    // 4) vT split: [4096,1024] fp32 -> [1024,4096] bf16 pair, per batch
    {
        dim3 g(DIMC / 32, NSEQ / 32, NB);
        transpose_conv_k<<<g, b256>>>(v, vth, vtl, NSEQ, DIMC, qkv, qkv);
    }

    // 5) scores = q @ k^T (fp32 out)
    {
        dim3 g(NSEQ / 128, NSEQ / 128, NB);
        tc_gemm2<0, false><<<g, b256, SMEM_BYTES>>>(qh, ql, kh, kl, nullptr,
                                                    s, nullptr, nullptr,
                                                    NSEQ, NSEQ, DIMC, qkv, qkv, ss);
    }

    // 6) softmax -> attn bf16 pair
    softmax2_k<<<M, b256>>>(s, ah, al, scale);

    // 7) ao = attn @ vT^T (bf16 pair out), K = 4096
    {
        dim3 g(DIMC / 128, NSEQ / 128, NB);
        tc_gemm2<1, false><<<g, b256, SMEM_BYTES>>>(ah, al, vth, vtl, nullptr,
                                                    nullptr, aoh, aol,
                                                    NSEQ, DIMC, NSEQ, ss, qkv, qkv);
    }

    // 8) out = ao @ WoT^T + bo (fp32 out)
    {
        dim3 g(DIMC / 128, M / 128, 1);
        tc_gemm2<0, true><<<g, b256, SMEM_BYTES>>>(aoh, aol, wth + 3*1048576, wtl + 3*1048576,
                                                   bo, out, nullptr, nullptr,
                                                   M, DIMC, DIMC, 0, 0, 0);
    }
}

// round 10
// speedup vs baseline: 1.4419x; 1.4419x over previous
#include <cuda_runtime.h>
#include <cuda_bf16.h>
#include <cstdint>

// ---------------------------------------------------------------------------
// NaiveAttention on GB300. B=4, N=4096, C=1024 fp32.
// R9: pre-split bf16 hi/lo operands + front-batched loader (MLP=16) +
// 3-stage SMEM pipeline. tcgen05 mainloop at the MMA floor.
// ---------------------------------------------------------------------------

#if !defined(__CUDA_ARCH__)
#define USE_TC 1
#elif defined(__CUDA_ARCH_FEAT_SM103_ALL) || defined(__CUDA_ARCH_FEAT_SM100_ALL) || \
      defined(__CUDA_ARCH_FEAT_SM101_ALL) || defined(__CUDA_ARCH_SPECIFIC__) || \
      defined(__CUDA_ARCH_FAMILY_SPECIFIC__)
#define USE_TC 1
#else
#define USE_TC 0
#endif

#define DIMC 1024
#define NSEQ 4096
#define NB   4

typedef __nv_bfloat16 bf16;

// Scratch (device globals — no allocation allowed).
__device__ bf16  g_xh [16777216], g_xl [16777216];
__device__ bf16  g_wth[4194304],  g_wtl[4194304];
__device__ bf16  g_qh [16777216], g_ql [16777216];
__device__ bf16  g_kh [16777216], g_kl [16777216];
__device__ float g_v  [16777216];
__device__ bf16  g_vth[16777216], g_vtl[16777216];
__device__ float g_s  [67108864];
__device__ bf16  g_ah [67108864], g_al [67108864];
__device__ bf16  g_aoh[16777216], g_aol[16777216];

#define KT 64
#define IDESC 0x8200490u   // f32 accum, bf16 x bf16, M=128, N=128
#define BUF_BYTES 65536    // Ahi(16K) Alo(16K) Bhi(16K) Blo(16K)
#define NSTAGE 3
#define SMEM_BYTES (2048 + NSTAGE * BUF_BYTES)

// ---- bf16 pack helpers (legal on base target too) -------------------------
__device__ __forceinline__ uint32_t pack_bf16(float lo, float hi) {
    uint32_t r;
    asm("cvt.rn.satfinite.bf16x2.f32 %0, %1, %2;" : "=r"(r) : "f"(hi), "f"(lo));
    return r;
}
__device__ __forceinline__ float bf16_rn_f32(float x) {
    uint32_t r;
    asm("cvt.rn.satfinite.bf16x2.f32 %0, %1, %1;" : "=r"(r) : "f"(x));
    return __uint_as_float(r << 16);
}

#if USE_TC
// ---------------------------------------------------------------------------
// sm_103a-only PTX helpers
// ---------------------------------------------------------------------------
__device__ __forceinline__ uint32_t smem_u32(const void* p) {
    uint32_t a;
    asm("{ .reg .u64 t; cvta.to.shared.u64 t, %1; cvt.u32.u64 %0, t; }"
        : "=r"(a) : "l"(p));
    return a;
}

#define MBAR_INIT(addr, cnt) \
    asm volatile("mbarrier.init.shared.b64 [%0], %1;" :: "r"(addr), "r"(cnt) : "memory")

#define MBAR_WAIT(addr, ph) do {                                              \
    uint32_t _m = (addr); uint32_t _p = (ph); uint32_t _done;                 \
    asm volatile("{\n\t.reg .pred p;\n\t"                                     \
        "mbarrier.try_wait.parity.acquire.cta.shared::cta.b64 p, [%1], %2;\n\t" \
        "selp.b32 %0, 1, 0, p;\n\t}"                                          \
        : "=r"(_done) : "r"(_m), "r"(_p) : "memory");                         \
    if (!_done) {                                                             \
        asm volatile("{\n\t.reg .pred P1;\n\t"                                \
            "WL_%=:\n\t"                                                      \
            "mbarrier.try_wait.parity.acquire.cta.shared::cta.b64 P1, [%0], %1, 0x989680;\n\t" \
            "@P1 bra.uni WD_%=;\n\t"                                          \
            "bra.uni WL_%=;\n\t"                                              \
            "WD_%=:\n\t}"                                                     \
            :: "r"(_m), "r"(_p) : "memory");                                  \
    }                                                                         \
} while (0)

#define TC_ALLOC(sm, n)   asm volatile("tcgen05.alloc.cta_group::1.sync.aligned.shared::cta.b32 [%0], %1;" :: "r"(sm), "r"(n) : "memory")
#define TC_DEALLOC(t, n)  asm volatile("tcgen05.dealloc.cta_group::1.sync.aligned.b32 %0, %1;" :: "r"(t), "r"(n))
#define TC_RELINQ()       asm volatile("tcgen05.relinquish_alloc_permit.cta_group::1.sync.aligned;")
#define TC_COMMIT(mb)     asm volatile("tcgen05.commit.cta_group::1.mbarrier::arrive::one.shared::cluster.b64 [%0];" :: "r"(mb) : "memory")
#define TC_FENCE_AFTER()  asm volatile("tcgen05.fence::after_thread_sync;" ::: "memory")
#define TC_FENCE_BEFORE() asm volatile("tcgen05.fence::before_thread_sync;" ::: "memory")
#define TC_WAIT_LD()      asm volatile("tcgen05.wait::ld.sync.aligned;" ::: "memory")
#define FENCE_ASYNC()     asm volatile("fence.proxy.async.shared::cta;" ::: "memory")

#define TC_LD_X32(r, a) \
    asm volatile("tcgen05.ld.sync.aligned.32x32b.x32.b32 " \
        "{%0, %1, %2, %3, %4, %5, %6, %7, %8, %9, %10, %11, %12, %13, %14, %15, " \
        " %16, %17, %18, %19, %20, %21, %22, %23, %24, %25, %26, %27, %28, %29, %30, %31}, [%32];" \
        : "=r"((r)[0]), "=r"((r)[1]), "=r"((r)[2]), "=r"((r)[3]), \
          "=r"((r)[4]), "=r"((r)[5]), "=r"((r)[6]), "=r"((r)[7]), \
          "=r"((r)[8]), "=r"((r)[9]), "=r"((r)[10]), "=r"((r)[11]), \
          "=r"((r)[12]), "=r"((r)[13]), "=r"((r)[14]), "=r"((r)[15]), \
          "=r"((r)[16]), "=r"((r)[17]), "=r"((r)[18]), "=r"((r)[19]), \
          "=r"((r)[20]), "=r"((r)[21]), "=r"((r)[22]), "=r"((r)[23]), \
          "=r"((r)[24]), "=r"((r)[25]), "=r"((r)[26]), "=r"((r)[27]), \
          "=r"((r)[28]), "=r"((r)[29]), "=r"((r)[30]), "=r"((r)[31]) \
        : "r"(a))

__device__ __forceinline__ void mma_f16_ss(uint32_t d, uint64_t a, uint64_t b,
                                           uint32_t idesc, uint32_t en) {
    asm volatile("{\n\t.reg .pred p;\n\tsetp.ne.u32 p, %4, 0;\n\t"
        "tcgen05.mma.cta_group::1.kind::f16 [%0], %1, %2, %3, {%5, %5, %5, %5}, p;\n\t}"
        :: "r"(d), "l"(a), "l"(b), "r"(idesc), "r"(en), "r"(0u) : "memory");
}

__device__ __forceinline__ uint64_t mk_desc(uint32_t addr) {
    const uint64_t base = (uint64_t(2) << 61) | (uint64_t(1) << 46)
                        | (uint64_t(64) << 32) | (uint64_t(1) << 16);
    return base | ((uint64_t)(addr >> 4) & 0x3FFF);
}

#define STS128(addr, v) \
    asm volatile("st.shared.v4.b32 [%0], {%1, %2, %3, %4};" \
        :: "r"(addr), "r"((v).x), "r"((v).y), "r"((v).z), "r"((v).w) : "memory")
#endif  // USE_TC

// ---------------------------------------------------------------------------
// GEMM:  C[z] = (Ahi+Alo)[z] @ (Bhi+Blo)[z]^T (+ bias), 3-product split.
//   A*: [M,K] bf16 K-major, B*: [N,K] bf16 K-major.
//   OUTM=0: write Cf fp32 [M,N].  OUTM=1: write Chi/Clo bf16 hi/lo pair.
//   128x128 CTA tile, 256 threads. M,N % 128 == 0, K % 64 == 0.
// ---------------------------------------------------------------------------
template <int OUTM, bool HAS_BIAS>
__global__ __launch_bounds__(256, 1)
void tc_gemm2(const bf16* __restrict__ Ahi, const bf16* __restrict__ Alo,
              const bf16* __restrict__ Bhi, const bf16* __restrict__ Blo,
              const float* __restrict__ bias,
              float* __restrict__ Cf, bf16* __restrict__ Chi, bf16* __restrict__ Clo,
              int M, int N, int K,
              long long sA, long long sB, long long sC)
{
    extern __shared__ char smem[];

    Ahi += (long long)blockIdx.z * sA;  Alo += (long long)blockIdx.z * sA;
    Bhi += (long long)blockIdx.z * sB;  Blo += (long long)blockIdx.z * sB;

    const int tid = threadIdx.x;
    const int m0  = blockIdx.y * 128;
    const int n0  = blockIdx.x * 128;

#if USE_TC
    const uint32_t sb    = smem_u32(smem);
    const uint32_t tiles = (sb + 32 + 1023) & ~1023u;
    char* tilesg = smem + (tiles - sb);
    const uint32_t mb[NSTAGE] = { sb, sb + 8, sb + 16 };
    const uint32_t tptr  = sb + 24;

    if (tid < 32) TC_ALLOC(tptr, 128);
    if (tid == 0) {
        MBAR_INIT(mb[0], 1); MBAR_INIT(mb[1], 1); MBAR_INIT(mb[2], 1);
    }
    __syncthreads();
    uint32_t tmem;
    asm volatile("ld.shared.b32 %0, [%1];" : "=r"(tmem) : "r"(tptr));

    const int nk = K / KT;
    int ph[NSTAGE] = { 0, 0, 0 };

    // loader geometry: thread -> (row, 64B half-row)
    const int lrow  = tid >> 1;
    const int lhalf = tid & 1;
    const long long lbase = (long long)lrow * K + lhalf * 32;

    int buf = 0;
    for (int t = 0; t < nk; t++) {
        const uint32_t sbase = tiles + buf * BUF_BYTES;

        if (t >= NSTAGE) { MBAR_WAIT(mb[buf], ph[buf]); ph[buf] ^= 1; }

        // ---- front-batched loads: 16 LDG.128 (MLP=16), then 16 STS.128 ----
        const bf16* pAh = Ahi + (long long)m0 * K + t * KT + lbase;
        const bf16* pAl = Alo + (long long)m0 * K + t * KT + lbase;
        const bf16* pBh = Bhi + (long long)n0 * K + t * KT + lbase;
        const bf16* pBl = Blo + (long long)n0 * K + t * KT + lbase;

        uint4 rg[16];
        #pragma unroll
        for (int j = 0; j < 4; j++) rg[ 0 + j] = *reinterpret_cast<const uint4*>(pAh + j * 8);
        #pragma unroll
        for (int j = 0; j < 4; j++) rg[ 4 + j] = *reinterpret_cast<const uint4*>(pAl + j * 8);
        #pragma unroll
        for (int j = 0; j < 4; j++) rg[ 8 + j] = *reinterpret_cast<const uint4*>(pBh + j * 8);
        #pragma unroll
        for (int j = 0; j < 4; j++) rg[12 + j] = *reinterpret_cast<const uint4*>(pBl + j * 8);

        const uint32_t off0 = (uint32_t)(lrow * 128 + lhalf * 64);
        #pragma unroll
        for (int r = 0; r < 4; r++) {
            #pragma unroll
            for (int j = 0; j < 4; j++) {
                uint32_t off = off0 + j * 16;
                uint32_t sw  = off ^ ((off >> 3) & 0x70);
                uint32_t addr = sbase + r * 16384 + sw;
                STS128(addr, rg[r * 4 + j]);
            }
        }
        FENCE_ASYNC();
        __syncthreads();

        // ---- 12 MMAs (3 splits x 4 K-steps of 16) ----
        if (tid == 0) {
            uint64_t ah = mk_desc(sbase);
            uint64_t al = mk_desc(sbase + 16384);
            uint64_t bh = mk_desc(sbase + 32768);
            uint64_t bl = mk_desc(sbase + 49152);
            #pragma unroll
            for (int kc = 0; kc < 4; kc++)
                mma_f16_ss(tmem, ah + kc * 2, bh + kc * 2, IDESC, (t | kc) != 0);
            #pragma unroll
            for (int kc = 0; kc < 4; kc++)
                mma_f16_ss(tmem, ah + kc * 2, bl + kc * 2, IDESC, 1);
            #pragma unroll
            for (int kc = 0; kc < 4; kc++)
                mma_f16_ss(tmem, al + kc * 2, bh + kc * 2, IDESC, 1);
            TC_COMMIT(mb[buf]);
        }

        buf = (buf == NSTAGE - 1) ? 0 : buf + 1;
    }

    // ---- drain: last commit covers all previously issued MMAs ----
    {
        int lastbuf = (nk - 1) % NSTAGE;
        MBAR_WAIT(mb[lastbuf], ph[lastbuf]);
    }
    TC_FENCE_AFTER();

    if (HAS_BIAS) {
        if (tid < 128) ((float*)tilesg)[tid] = bias[n0 + tid];
        __syncthreads();
    }

    if (tid < 128) {
        uint32_t d[128];
        TC_LD_X32(d +  0, tmem +  0);
        TC_LD_X32(d + 32, tmem + 32);
        TC_LD_X32(d + 64, tmem + 64);
        TC_LD_X32(d + 96, tmem + 96);
        TC_WAIT_LD();
        TC_FENCE_BEFORE();
        const int row = m0 + tid;
        const float* bsm = (const float*)tilesg;

        if (OUTM == 0) {
            float* cp = Cf + (long long)blockIdx.z * sC + (long long)row * N + n0;
            #pragma unroll
            for (int c = 0; c < 128; c += 4) {
                float4 o;
                o.x = __uint_as_float(d[c + 0]);
                o.y = __uint_as_float(d[c + 1]);
                o.z = __uint_as_float(d[c + 2]);
                o.w = __uint_as_float(d[c + 3]);
                if (HAS_BIAS) {
                    o.x += bsm[c + 0]; o.y += bsm[c + 1];
                    o.z += bsm[c + 2]; o.w += bsm[c + 3];
                }
                *reinterpret_cast<float4*>(cp + c) = o;
            }
        } else {
            const long long rb = (long long)blockIdx.z * sC + (long long)row * N + n0;
            #pragma unroll
            for (int c = 0; c < 128; c += 8) {
                float v[8];
                #pragma unroll
                for (int j = 0; j < 8; j++) {
                    v[j] = __uint_as_float(d[c + j]);
                    if (HAS_BIAS) v[j] += bsm[c + j];
                }
                uint4 hw, lw;
                hw.x = pack_bf16(v[0], v[1]); hw.y = pack_bf16(v[2], v[3]);
                hw.z = pack_bf16(v[4], v[5]); hw.w = pack_bf16(v[6], v[7]);
                float l[8];
                #pragma unroll
                for (int j = 0; j < 8; j++) l[j] = v[j] - bf16_rn_f32(v[j]);
                lw.x = pack_bf16(l[0], l[1]); lw.y = pack_bf16(l[2], l[3]);
                lw.z = pack_bf16(l[4], l[5]); lw.w = pack_bf16(l[6], l[7]);
                *reinterpret_cast<uint4*>(Chi + rb + c) = hw;
                *reinterpret_cast<uint4*>(Clo + rb + c) = lw;
            }
        }
    }

    __syncthreads();
    if (tid == 0) {
        asm volatile("mbarrier.inval.shared.b64 [%0];" :: "r"(mb[0]) : "memory");
        asm volatile("mbarrier.inval.shared.b64 [%0];" :: "r"(mb[1]) : "memory");
        asm volatile("mbarrier.inval.shared.b64 [%0];" :: "r"(mb[2]) : "memory");
    }
    __syncthreads();
    if (tid < 32) { TC_RELINQ(); TC_DEALLOC(tmem, 128); }

#else
    // ================= SIMT fallback (base target; never selected) =========
    float (*As)[128] = reinterpret_cast<float (*)[128]>(smem);
    float (*Bs)[128] = reinterpret_cast<float (*)[128]>(smem + 4096);

    const int ty = tid >> 4, tx = tid & 15;
    const int aRow = tid >> 1, aCol = (tid & 1) * 4;
    float acc[8][8] = {};

    for (int k0 = 0; k0 < K; k0 += 8) {
        #pragma unroll
        for (int e = 0; e < 4; e++) {
            long long ia = (long long)(m0 + aRow) * K + k0 + aCol + e;
            As[aCol + e][aRow] = __bfloat162float(Ahi[ia]) + __bfloat162float(Alo[ia]);
            long long ib = (long long)(n0 + aRow) * K + k0 + aCol + e;
            Bs[aCol + e][aRow] = __bfloat162float(Bhi[ib]) + __bfloat162float(Blo[ib]);
        }
        __syncthreads();
        #pragma unroll
        for (int kk = 0; kk < 8; kk++) {
            float ra[8], rb[8];
            #pragma unroll
            for (int i = 0; i < 8; i++) ra[i] = As[kk][ty * 8 + i];
            #pragma unroll
            for (int j = 0; j < 8; j++) rb[j] = Bs[kk][tx * 8 + j];
            #pragma unroll
            for (int i = 0; i < 8; i++)
                #pragma unroll
                for (int j = 0; j < 8; j++)
                    acc[i][j] = fmaf(ra[i], rb[j], acc[i][j]);
        }
        __syncthreads();
    }
    #pragma unroll
    for (int i = 0; i < 8; i++) {
        const int row = m0 + ty * 8 + i;
        #pragma unroll
        for (int j = 0; j < 8; j++) {
            const int col = n0 + tx * 8 + j;
            float val = acc[i][j] + (HAS_BIAS ? bias[col] : 0.f);
            long long o = (long long)blockIdx.z * sC + (long long)row * N + col;
            if (OUTM == 0) {
                Cf[o] = val;
            } else {
                float h = bf16_rn_f32(val);
                Chi[o] = __float2bfloat16(val);
                Clo[o] = __float2bfloat16(val - h);
            }
        }
    }
#endif
}

// ---------------------------------------------------------------------------
// Elementwise fp32 -> bf16 hi/lo split (n4 = count of float4 groups)
// ---------------------------------------------------------------------------
__global__ __launch_bounds__(256)
void conv_k(const float* __restrict__ in, bf16* __restrict__ oh,
            bf16* __restrict__ ol, long long n4)
{
    long long idx = (long long)blockIdx.x * blockDim.x + threadIdx.x;
    if (idx >= n4) return;
    float4 v = reinterpret_cast<const float4*>(in)[idx];
    uint2 hw, lw;
    hw.x = pack_bf16(v.x, v.y); hw.y = pack_bf16(v.z, v.w);
    lw.x = pack_bf16(v.x - bf16_rn_f32(v.x), v.y - bf16_rn_f32(v.y));
    lw.y = pack_bf16(v.z - bf16_rn_f32(v.z), v.w - bf16_rn_f32(v.w));
    reinterpret_cast<uint2*>(oh)[idx] = hw;
    reinterpret_cast<uint2*>(ol)[idx] = lw;
}

// ---------------------------------------------------------------------------
// 32x32 tiled transpose fp32 -> bf16 hi/lo:  out[c][r] = split(in[r][c])
// ---------------------------------------------------------------------------
__global__ __launch_bounds__(256)
void transpose_conv_k(const float* __restrict__ in,
                      bf16* __restrict__ oh, bf16* __restrict__ ol,
                      int R, int Cc, long long sIn, long long sOut)
{
    __shared__ float t[32][33];
    in += (long long)blockIdx.z * sIn;
    const long long ob = (long long)blockIdx.z * sOut;
    const int r0 = blockIdx.y * 32, c0 = blockIdx.x * 32;
    const int tx = threadIdx.x & 31, ty = threadIdx.x >> 5;
    #pragma unroll
    for (int i = 0; i < 32; i += 8)
        t[ty + i][tx] = in[(long long)(r0 + ty + i) * Cc + c0 + tx];
    __syncthreads();
    #pragma unroll
    for (int i = 0; i < 32; i += 8) {
        float v = t[tx][ty + i];
        float h = bf16_rn_f32(v);
        long long o = ob + (long long)(c0 + ty + i) * R + r0 + tx;
        oh[o] = __float2bfloat16(v);
        ol[o] = __float2bfloat16(v - h);
    }
}

// ---------------------------------------------------------------------------
// Row softmax (rows of 4096, scale folded), writes attn as bf16 hi/lo.
// ---------------------------------------------------------------------------
__global__ __launch_bounds__(256)
void softmax2_k(const float* __restrict__ S, bf16* __restrict__ AH,
                bf16* __restrict__ AL, float scale)
{
    const float* row = S + (long long)blockIdx.x * 4096;
    const long long ob = (long long)blockIdx.x * 4096;
    const int t = threadIdx.x;
    const int base = t * 16;
    __shared__ float red[256];

    float vals[16];
    float m = -1e30f;
    #pragma unroll
    for (int i = 0; i < 4; i++) {
        float4 v = reinterpret_cast<const float4*>(row + base)[i];
        vals[i * 4 + 0] = v.x; vals[i * 4 + 1] = v.y;
        vals[i * 4 + 2] = v.z; vals[i * 4 + 3] = v.w;
    }
    #pragma unroll
    for (int i = 0; i < 16; i++) m = fmaxf(m, vals[i]);
    red[t] = m;
    __syncthreads();
    #pragma unroll
    for (int s = 128; s > 0; s >>= 1) {
        if (t < s) red[t] = fmaxf(red[t], red[t + s]);
        __syncthreads();
    }
    m = red[0];
    __syncthreads();

    float sum = 0.f;
    #pragma unroll
    for (int i = 0; i < 16; i++) {
        vals[i] = __expf(scale * (vals[i] - m));
        sum += vals[i];
    }
    red[t] = sum;
    __syncthreads();
    #pragma unroll
    for (int s = 128; s > 0; s >>= 1) {
        if (t < s) red[t] += red[t + s];
        __syncthreads();
    }
    const float inv = 1.0f / red[0];

    uint4 hw[2], lw[2];
    #pragma unroll
    for (int g = 0; g < 2; g++) {
        float v[8], l[8];
        #pragma unroll
        for (int j = 0; j < 8; j++) {
            v[j] = vals[g * 8 + j] * inv;
            l[j] = v[j] - bf16_rn_f32(v[j]);
        }
        hw[g].x = pack_bf16(v[0], v[1]); hw[g].y = pack_bf16(v[2], v[3]);
        hw[g].z = pack_bf16(v[4], v[5]); hw[g].w = pack_bf16(v[6], v[7]);
        lw[g].x = pack_bf16(l[0], l[1]); lw[g].y = pack_bf16(l[2], l[3]);
        lw[g].z = pack_bf16(l[4], l[5]); lw[g].w = pack_bf16(l[6], l[7]);
    }
    reinterpret_cast<uint4*>(AH + ob + base)[0] = hw[0];
    reinterpret_cast<uint4*>(AH + ob + base)[1] = hw[1];
    reinterpret_cast<uint4*>(AL + ob + base)[0] = lw[0];
    reinterpret_cast<uint4*>(AL + ob + base)[1] = lw[1];
}

// ---------------------------------------------------------------------------
extern "C" void kernel_launch(void* const* d_in, const int* in_sizes, int n_in,
                              void* d_out, int out_size)
{
    const float* x  = (const float*)d_in[0];
    const float* Wq = (const float*)d_in[1];
    const float* bq = (const float*)d_in[2];
    const float* Wk = (const float*)d_in[3];
    const float* bk = (const float*)d_in[4];
    const float* Wv = (const float*)d_in[5];
    const float* bv = (const float*)d_in[6];
    const float* Wo = (const float*)d_in[7];
    const float* bo = (const float*)d_in[8];
    float* out = (float*)d_out;

    const int M = NB * NSEQ;
    const float scale = 0.03125f;

    bf16 *xh, *xl, *wth, *wtl, *qh, *ql, *kh, *kl, *vth, *vtl, *ah, *al, *aoh, *aol;
    float *v, *s;
    cudaGetSymbolAddress((void**)&xh,  g_xh);  cudaGetSymbolAddress((void**)&xl,  g_xl);
    cudaGetSymbolAddress((void**)&wth, g_wth); cudaGetSymbolAddress((void**)&wtl, g_wtl);
    cudaGetSymbolAddress((void**)&qh,  g_qh);  cudaGetSymbolAddress((void**)&ql,  g_ql);
    cudaGetSymbolAddress((void**)&kh,  g_kh);  cudaGetSymbolAddress((void**)&kl,  g_kl);
    cudaGetSymbolAddress((void**)&v,   g_v);
    cudaGetSymbolAddress((void**)&vth, g_vth); cudaGetSymbolAddress((void**)&vtl, g_vtl);
    cudaGetSymbolAddress((void**)&s,   g_s);
    cudaGetSymbolAddress((void**)&ah,  g_ah);  cudaGetSymbolAddress((void**)&al,  g_al);
    cudaGetSymbolAddress((void**)&aoh, g_aoh); cudaGetSymbolAddress((void**)&aol, g_aol);

    cudaFuncSetAttribute((const void*)tc_gemm2<0, true>,  cudaFuncAttributeMaxDynamicSharedMemorySize, SMEM_BYTES);
    cudaFuncSetAttribute((const void*)tc_gemm2<0, false>, cudaFuncAttributeMaxDynamicSharedMemorySize, SMEM_BYTES);
    cudaFuncSetAttribute((const void*)tc_gemm2<1, true>,  cudaFuncAttributeMaxDynamicSharedMemorySize, SMEM_BYTES);
    cudaFuncSetAttribute((const void*)tc_gemm2<1, false>, cudaFuncAttributeMaxDynamicSharedMemorySize, SMEM_BYTES);

    const long long qkv = (long long)NSEQ * DIMC;
    const long long ss  = (long long)NSEQ * NSEQ;

    dim3 b256(256);

    // 1) split x -> xh/xl
    conv_k<<<16384, b256>>>(x, xh, xl, 4194304);

    // 2) transpose+split weights
    {
        dim3 g(32, 32, 1);
        transpose_conv_k<<<g, b256>>>(Wq, wth + 0*1048576, wtl + 0*1048576, DIMC, DIMC, 0, 0);
        transpose_conv_k<<<g, b256>>>(Wk, wth + 1*1048576, wtl + 1*1048576, DIMC, DIMC, 0, 0);
        transpose_conv_k<<<g, b256>>>(Wv, wth + 2*1048576, wtl + 2*1048576, DIMC, DIMC, 0, 0);
        transpose_conv_k<<<g, b256>>>(Wo, wth + 3*1048576, wtl + 3*1048576, DIMC, DIMC, 0, 0);
    }

    // 3) q,k (bf16 pair out) and v (fp32 out) projections
    {
        dim3 g(DIMC / 128, M / 128, 1);
        tc_gemm2<1, true><<<g, b256, SMEM_BYTES>>>(xh, xl, wth + 0*1048576, wtl + 0*1048576,
                                                   bq, nullptr, qh, ql, M, DIMC, DIMC, 0, 0, 0);
        tc_gemm2<1, true><<<g, b256, SMEM_BYTES>>>(xh, xl, wth + 1*1048576, wtl + 1*1048576,
                                                   bk, nullptr, kh, kl, M, DIMC, DIMC, 0, 0, 0);
        tc_gemm2<0, true><<<g, b256, SMEM_BYTES>>>(xh, xl, wth + 2*1048576, wtl + 2*1048576,
                                                   bv, v, nullptr, nullptr, M, DIMC, DIMC, 0, 0, 0);
    }

    // 4) vT split per batch
    {
        dim3 g(DIMC / 32, NSEQ / 32, NB);
        transpose_conv_k<<<g, b256>>>(v, vth, vtl, NSEQ, DIMC, qkv, qkv);
    }

    // 5) scores = q @ k^T (fp32 out)
    {
        dim3 g(NSEQ / 128, NSEQ / 128, NB);
        tc_gemm2<0, false><<<g, b256, SMEM_BYTES>>>(qh, ql, kh, kl, nullptr,
                                                    s, nullptr, nullptr,
                                                    NSEQ, NSEQ, DIMC, qkv, qkv, ss);
    }

    // 6) softmax -> attn bf16 pair
    softmax2_k<<<M, b256>>>(s, ah, al, scale);

    // 7) ao = attn @ vT^T (bf16 pair out), K = 4096
    {
        dim3 g(DIMC / 128, NSEQ / 128, NB);
        tc_gemm2<1, false><<<g, b256, SMEM_BYTES>>>(ah, al, vth, vtl, nullptr,
                                                    nullptr, aoh, aol,
                                                    NSEQ, DIMC, NSEQ, ss, qkv, qkv);
    }

    // 8) out = ao @ WoT^T + bo (fp32 out)
    {
        dim3 g(DIMC / 128, M / 128, 1);
        tc_gemm2<0, true><<<g, b256, SMEM_BYTES>>>(aoh, aol, wth + 3*1048576, wtl + 3*1048576,
                                                   bo, out, nullptr, nullptr,
                                                   M, DIMC, DIMC, 0, 0, 0);
    }
}

// round 11
// speedup vs baseline: 1.9985x; 1.3861x over previous
#include <cuda_runtime.h>
#include <cuda_bf16.h>
#include <cstdint>

// ---------------------------------------------------------------------------
// NaiveAttention on GB300. B=4, N=4096, C=1024 fp32.
// R11: pre-split bf16 hi/lo + 128x256 CTA tiles (N=256 MMA) + cp.async
// loader (no data registers) + 2-stage pipeline. Attacks the LTS-cap bound.
// ---------------------------------------------------------------------------

#if !defined(__CUDA_ARCH__)
#define USE_TC 1
#elif defined(__CUDA_ARCH_FEAT_SM103_ALL) || defined(__CUDA_ARCH_FEAT_SM100_ALL) || \
      defined(__CUDA_ARCH_FEAT_SM101_ALL) || defined(__CUDA_ARCH_SPECIFIC__) || \
      defined(__CUDA_ARCH_FAMILY_SPECIFIC__)
#define USE_TC 1
#else
#define USE_TC 0
#endif

#define DIMC 1024
#define NSEQ 4096
#define NB   4

typedef __nv_bfloat16 bf16;

// Scratch (device globals — no allocation allowed).
__device__ bf16  g_xh [16777216], g_xl [16777216];
__device__ bf16  g_wth[4194304],  g_wtl[4194304];
__device__ bf16  g_qh [16777216], g_ql [16777216];
__device__ bf16  g_kh [16777216], g_kl [16777216];
__device__ float g_v  [16777216];
__device__ bf16  g_vth[16777216], g_vtl[16777216];
__device__ float g_s  [67108864];
__device__ bf16  g_ah [67108864], g_al [67108864];
__device__ bf16  g_aoh[16777216], g_aol[16777216];

#define KT 64
#define BN 256
#define IDESC2 0x8400490u  // f32 accum, bf16 x bf16, M=128, N=256
// Stage: Ahi 16K @0, Alo 16K @16K, Bhi 32K @32K, Blo 32K @64K
#define BUF_BYTES 98304
#define NSTAGE 2
#define SMEM_BYTES (2048 + NSTAGE * BUF_BYTES)

// ---- bf16 helpers (legal on base target too) ------------------------------
__device__ __forceinline__ uint32_t pack_bf16(float lo, float hi) {
    uint32_t r;
    asm("cvt.rn.satfinite.bf16x2.f32 %0, %1, %2;" : "=r"(r) : "f"(hi), "f"(lo));
    return r;
}
__device__ __forceinline__ float bf16_rn_f32(float x) {
    uint32_t r;
    asm("cvt.rn.satfinite.bf16x2.f32 %0, %1, %1;" : "=r"(r) : "f"(x));
    return __uint_as_float(r << 16);
}

#if USE_TC
// ---------------------------------------------------------------------------
// sm_103a-only PTX helpers
// ---------------------------------------------------------------------------
__device__ __forceinline__ uint32_t smem_u32(const void* p) {
    uint32_t a;
    asm("{ .reg .u64 t; cvta.to.shared.u64 t, %1; cvt.u32.u64 %0, t; }"
        : "=r"(a) : "l"(p));
    return a;
}

#define MBAR_INIT(addr, cnt) \
    asm volatile("mbarrier.init.shared.b64 [%0], %1;" :: "r"(addr), "r"(cnt) : "memory")

#define MBAR_WAIT(addr, ph) do {                                              \
    uint32_t _m = (addr); uint32_t _p = (ph); uint32_t _done;                 \
    asm volatile("{\n\t.reg .pred p;\n\t"                                     \
        "mbarrier.try_wait.parity.acquire.cta.shared::cta.b64 p, [%1], %2;\n\t" \
        "selp.b32 %0, 1, 0, p;\n\t}"                                          \
        : "=r"(_done) : "r"(_m), "r"(_p) : "memory");                         \
    if (!_done) {                                                             \
        asm volatile("{\n\t.reg .pred P1;\n\t"                                \
            "WL_%=:\n\t"                                                      \
            "mbarrier.try_wait.parity.acquire.cta.shared::cta.b64 P1, [%0], %1, 0x989680;\n\t" \
            "@P1 bra.uni WD_%=;\n\t"                                          \
            "bra.uni WL_%=;\n\t"                                              \
            "WD_%=:\n\t}"                                                     \
            :: "r"(_m), "r"(_p) : "memory");                                  \
    }                                                                         \
} while (0)

#define TC_ALLOC(sm, n)   asm volatile("tcgen05.alloc.cta_group::1.sync.aligned.shared::cta.b32 [%0], %1;" :: "r"(sm), "r"(n) : "memory")
#define TC_DEALLOC(t, n)  asm volatile("tcgen05.dealloc.cta_group::1.sync.aligned.b32 %0, %1;" :: "r"(t), "r"(n))
#define TC_RELINQ()       asm volatile("tcgen05.relinquish_alloc_permit.cta_group::1.sync.aligned;")
#define TC_COMMIT(mb)     asm volatile("tcgen05.commit.cta_group::1.mbarrier::arrive::one.shared::cluster.b64 [%0];" :: "r"(mb) : "memory")
#define TC_FENCE_AFTER()  asm volatile("tcgen05.fence::after_thread_sync;" ::: "memory")
#define TC_FENCE_BEFORE() asm volatile("tcgen05.fence::before_thread_sync;" ::: "memory")
#define TC_WAIT_LD()      asm volatile("tcgen05.wait::ld.sync.aligned;" ::: "memory")
#define FENCE_ASYNC()     asm volatile("fence.proxy.async.shared::cta;" ::: "memory")

#define CP_ASYNC16(sm, gp) \
    asm volatile("cp.async.cg.shared.global [%0], [%1], 16;" :: "r"(sm), "l"(gp) : "memory")
#define CP_COMMIT() asm volatile("cp.async.commit_group;" ::: "memory")
#define CP_WAIT1()  asm volatile("cp.async.wait_group 1;" ::: "memory")

#define TC_LD_X32(r, a) \
    asm volatile("tcgen05.ld.sync.aligned.32x32b.x32.b32 " \
        "{%0, %1, %2, %3, %4, %5, %6, %7, %8, %9, %10, %11, %12, %13, %14, %15, " \
        " %16, %17, %18, %19, %20, %21, %22, %23, %24, %25, %26, %27, %28, %29, %30, %31}, [%32];" \
        : "=r"((r)[0]), "=r"((r)[1]), "=r"((r)[2]), "=r"((r)[3]), \
          "=r"((r)[4]), "=r"((r)[5]), "=r"((r)[6]), "=r"((r)[7]), \
          "=r"((r)[8]), "=r"((r)[9]), "=r"((r)[10]), "=r"((r)[11]), \
          "=r"((r)[12]), "=r"((r)[13]), "=r"((r)[14]), "=r"((r)[15]), \
          "=r"((r)[16]), "=r"((r)[17]), "=r"((r)[18]), "=r"((r)[19]), \
          "=r"((r)[20]), "=r"((r)[21]), "=r"((r)[22]), "=r"((r)[23]), \
          "=r"((r)[24]), "=r"((r)[25]), "=r"((r)[26]), "=r"((r)[27]), \
          "=r"((r)[28]), "=r"((r)[29]), "=r"((r)[30]), "=r"((r)[31]) \
        : "r"(a))

__device__ __forceinline__ void mma_f16_ss(uint32_t d, uint64_t a, uint64_t b,
                                           uint32_t idesc, uint32_t en) {
    asm volatile("{\n\t.reg .pred p;\n\tsetp.ne.u32 p, %4, 0;\n\t"
        "tcgen05.mma.cta_group::1.kind::f16 [%0], %1, %2, %3, {%5, %5, %5, %5}, p;\n\t}"
        :: "r"(d), "l"(a), "l"(b), "r"(idesc), "r"(en), "r"(0u) : "memory");
}

__device__ __forceinline__ uint64_t mk_desc(uint32_t addr) {
    const uint64_t base = (uint64_t(2) << 61) | (uint64_t(1) << 46)
                        | (uint64_t(64) << 32) | (uint64_t(1) << 16);
    return base | ((uint64_t)(addr >> 4) & 0x3FFF);
}

__device__ __forceinline__ uint32_t sw128(uint32_t off) {
    return off ^ ((off >> 3) & 0x70);
}
#endif  // USE_TC

// ---------------------------------------------------------------------------
// GEMM:  C[z] = (Ahi+Alo)[z] @ (Bhi+Blo)[z]^T (+ bias), 3-product split.
//   A*: [M,K] bf16 K-major, B*: [N,K] bf16 K-major.
//   OUTM=0: Cf fp32.  OUTM=1: Chi/Clo bf16 hi/lo.
//   CTA tile 128(M) x 256(N), 256 threads. M%128==0, N%256==0, K%64==0.
// ---------------------------------------------------------------------------
template <int OUTM, bool HAS_BIAS>
__global__ __launch_bounds__(256, 1)
void tc_gemm3(const bf16* __restrict__ Ahi, const bf16* __restrict__ Alo,
              const bf16* __restrict__ Bhi, const bf16* __restrict__ Blo,
              const float* __restrict__ bias,
              float* __restrict__ Cf, bf16* __restrict__ Chi, bf16* __restrict__ Clo,
              int M, int N, int K,
              long long sA, long long sB, long long sC)
{
    extern __shared__ char smem[];

    Ahi += (long long)blockIdx.z * sA;  Alo += (long long)blockIdx.z * sA;
    Bhi += (long long)blockIdx.z * sB;  Blo += (long long)blockIdx.z * sB;

    const int tid = threadIdx.x;
    const int m0  = blockIdx.y * 128;
    const int n0  = blockIdx.x * BN;

#if USE_TC
    const uint32_t sb    = smem_u32(smem);
    const uint32_t tiles = (sb + 32 + 1023) & ~1023u;
    char* tilesg = smem + (tiles - sb);
    const uint32_t mb[NSTAGE] = { sb, sb + 8 };
    const uint32_t tptr = sb + 16;

    if (tid < 32) TC_ALLOC(tptr, 256);
    if (tid == 0) { MBAR_INIT(mb[0], 1); MBAR_INIT(mb[1], 1); }
    __syncthreads();
    uint32_t tmem;
    asm volatile("ld.shared.b32 %0, [%1];" : "=r"(tmem) : "r"(tptr));

    const int nk = K / KT;
    int ph[NSTAGE] = { 0, 0 };

    // loader geometry: 2 threads per row; each thread owns a 64B half-row.
    const int lrow  = tid >> 1;          // 0..127
    const int lhalf = tid & 1;
    const long long gudge = (long long)lrow * K + lhalf * 32;  // element offset
    const uint32_t soffA = (uint32_t)(lrow * 128 + lhalf * 64);

    // issue all cp.async for tile tt into stage buffer `sbase`
    auto load_tile = [&](int tt, uint32_t sbase) {
        const long long kof = (long long)tt * KT;
        const bf16* pAh = Ahi + (long long)m0 * K + kof + gudge;
        const bf16* pAl = Alo + (long long)m0 * K + kof + gudge;
        #pragma unroll
        for (int j = 0; j < 4; j++)
            CP_ASYNC16(sbase + sw128(soffA + j * 16), pAh + j * 8);
        #pragma unroll
        for (int j = 0; j < 4; j++)
            CP_ASYNC16(sbase + 16384 + sw128(soffA + j * 16), pAl + j * 8);
        // B: rows lrow and lrow+128 of the 256-row tile
        #pragma unroll
        for (int r = 0; r < 2; r++) {
            const long long grow = (long long)(n0 + lrow + r * 128) * K + kof + lhalf * 32;
            const uint32_t soffB = (uint32_t)((lrow + r * 128) * 128 + lhalf * 64);
            const bf16* pBh = Bhi + grow;
            const bf16* pBl = Blo + grow;
            #pragma unroll
            for (int j = 0; j < 4; j++)
                CP_ASYNC16(sbase + 32768 + sw128(soffB + j * 16), pBh + j * 8);
            #pragma unroll
            for (int j = 0; j < 4; j++)
                CP_ASYNC16(sbase + 65536 + sw128(soffB + j * 16), pBl + j * 8);
        }
    };

    // prologue: tile 0 -> buf 0
    load_tile(0, tiles);
    CP_COMMIT();

    for (int t = 0; t < nk; t++) {
        const int buf = t & 1;
        const uint32_t sbase = tiles + buf * BUF_BYTES;

        // issue loads for t+1 (into the other buffer)
        if (t + 1 < nk) {
            const int nbuf = (t + 1) & 1;
            if (t + 1 >= NSTAGE) { MBAR_WAIT(mb[nbuf], ph[nbuf]); ph[nbuf] ^= 1; }
            load_tile(t + 1, tiles + nbuf * BUF_BYTES);
        }
        CP_COMMIT();              // always commit (possibly-empty) group
        CP_WAIT1();               // tile t's group is now complete
        FENCE_ASYNC();
        __syncthreads();

        // 12 MMAs (3 splits x 4 K-steps of 16), N=256 each
        if (tid == 0) {
            uint64_t ah = mk_desc(sbase);
            uint64_t al = mk_desc(sbase + 16384);
            uint64_t bh = mk_desc(sbase + 32768);
            uint64_t bl = mk_desc(sbase + 65536);
            #pragma unroll
            for (int kc = 0; kc < 4; kc++)
                mma_f16_ss(tmem, ah + kc * 2, bh + kc * 2, IDESC2, (t | kc) != 0);
            #pragma unroll
            for (int kc = 0; kc < 4; kc++)
                mma_f16_ss(tmem, ah + kc * 2, bl + kc * 2, IDESC2, 1);
            #pragma unroll
            for (int kc = 0; kc < 4; kc++)
                mma_f16_ss(tmem, al + kc * 2, bh + kc * 2, IDESC2, 1);
            TC_COMMIT(mb[buf]);
        }
    }

    // drain: last commit covers all previously issued MMAs
    {
        const int lastbuf = (nk - 1) & 1;
        MBAR_WAIT(mb[lastbuf], ph[lastbuf]);
    }
    TC_FENCE_AFTER();

    if (HAS_BIAS) {
        ((float*)tilesg)[tid] = bias[n0 + tid];   // 256 floats
        __syncthreads();
    }

    // epilogue: 128 threads read 2 x 128 TMEM cols
    if (tid < 128) {
        const int row = m0 + tid;
        const float* bsm = (const float*)tilesg;
        #pragma unroll
        for (int h = 0; h < 2; h++) {
            uint32_t d[128];
            TC_LD_X32(d +  0, tmem + h * 128 +  0);
            TC_LD_X32(d + 32, tmem + h * 128 + 32);
            TC_LD_X32(d + 64, tmem + h * 128 + 64);
            TC_LD_X32(d + 96, tmem + h * 128 + 96);
            TC_WAIT_LD();
            TC_FENCE_BEFORE();

            if (OUTM == 0) {
                float* cp = Cf + (long long)blockIdx.z * sC
                          + (long long)row * N + n0 + h * 128;
                #pragma unroll
                for (int c = 0; c < 128; c += 4) {
                    float4 o;
                    o.x = __uint_as_float(d[c + 0]);
                    o.y = __uint_as_float(d[c + 1]);
                    o.z = __uint_as_float(d[c + 2]);
                    o.w = __uint_as_float(d[c + 3]);
                    if (HAS_BIAS) {
                        o.x += bsm[h * 128 + c + 0]; o.y += bsm[h * 128 + c + 1];
                        o.z += bsm[h * 128 + c + 2]; o.w += bsm[h * 128 + c + 3];
                    }
                    *reinterpret_cast<float4*>(cp + c) = o;
                }
            } else {
                const long long rb = (long long)blockIdx.z * sC
                                   + (long long)row * N + n0 + h * 128;
                #pragma unroll
                for (int c = 0; c < 128; c += 8) {
                    float v[8];
                    #pragma unroll
                    for (int j = 0; j < 8; j++) {
                        v[j] = __uint_as_float(d[c + j]);
                        if (HAS_BIAS) v[j] += bsm[h * 128 + c + j];
                    }
                    uint4 hw, lw;
                    hw.x = pack_bf16(v[0], v[1]); hw.y = pack_bf16(v[2], v[3]);
                    hw.z = pack_bf16(v[4], v[5]); hw.w = pack_bf16(v[6], v[7]);
                    float l[8];
                    #pragma unroll
                    for (int j = 0; j < 8; j++) l[j] = v[j] - bf16_rn_f32(v[j]);
                    lw.x = pack_bf16(l[0], l[1]); lw.y = pack_bf16(l[2], l[3]);
                    lw.z = pack_bf16(l[4], l[5]); lw.w = pack_bf16(l[6], l[7]);
                    *reinterpret_cast<uint4*>(Chi + rb + c) = hw;
                    *reinterpret_cast<uint4*>(Clo + rb + c) = lw;
                }
            }
        }
    }

    __syncthreads();
    if (tid == 0) {
        asm volatile("mbarrier.inval.shared.b64 [%0];" :: "r"(mb[0]) : "memory");
        asm volatile("mbarrier.inval.shared.b64 [%0];" :: "r"(mb[1]) : "memory");
    }
    __syncthreads();
    if (tid < 32) { TC_RELINQ(); TC_DEALLOC(tmem, 256); }

#else
    // ================= SIMT fallback (base target; never selected) =========
    float (*As)[128] = reinterpret_cast<float (*)[128]>(smem);
    float (*Bs)[128] = reinterpret_cast<float (*)[128]>(smem + 4096);

    const int ty = tid >> 4, tx = tid & 15;
    const int aRow = tid >> 1, aCol = (tid & 1) * 4;

    for (int half = 0; half < 2; half++) {
        const int n0h = n0 + half * 128;
        float acc[8][8] = {};
        for (int k0 = 0; k0 < K; k0 += 8) {
            #pragma unroll
            for (int e = 0; e < 4; e++) {
                long long ia = (long long)(m0 + aRow) * K + k0 + aCol + e;
                As[aCol + e][aRow] = __bfloat162float(Ahi[ia]) + __bfloat162float(Alo[ia]);
                long long ib = (long long)(n0h + aRow) * K + k0 + aCol + e;
                Bs[aCol + e][aRow] = __bfloat162float(Bhi[ib]) + __bfloat162float(Blo[ib]);
            }
            __syncthreads();
            #pragma unroll
            for (int kk = 0; kk < 8; kk++) {
                float ra[8], rb[8];
                #pragma unroll
                for (int i = 0; i < 8; i++) ra[i] = As[kk][ty * 8 + i];
                #pragma unroll
                for (int j = 0; j < 8; j++) rb[j] = Bs[kk][tx * 8 + j];
                #pragma unroll
                for (int i = 0; i < 8; i++)
                    #pragma unroll
                    for (int j = 0; j < 8; j++)
                        acc[i][j] = fmaf(ra[i], rb[j], acc[i][j]);
            }
            __syncthreads();
        }
        #pragma unroll
        for (int i = 0; i < 8; i++) {
            const int row = m0 + ty * 8 + i;
            #pragma unroll
            for (int j = 0; j < 8; j++) {
                const int col = n0h + tx * 8 + j;
                float val = acc[i][j] + (HAS_BIAS ? bias[col] : 0.f);
                long long o = (long long)blockIdx.z * sC + (long long)row * N + col;
                if (OUTM == 0) {
                    Cf[o] = val;
                } else {
                    float hh = bf16_rn_f32(val);
                    Chi[o] = __float2bfloat16(val);
                    Clo[o] = __float2bfloat16(val - hh);
                }
            }
        }
        __syncthreads();
    }
#endif
}

// ---------------------------------------------------------------------------
// Elementwise fp32 -> bf16 hi/lo split (n4 = count of float4 groups)
// ---------------------------------------------------------------------------
__global__ __launch_bounds__(256)
void conv_k(const float* __restrict__ in, bf16* __restrict__ oh,
            bf16* __restrict__ ol, long long n4)
{
    long long idx = (long long)blockIdx.x * blockDim.x + threadIdx.x;
    if (idx >= n4) return;
    float4 v = reinterpret_cast<const float4*>(in)[idx];
    uint2 hw, lw;
    hw.x = pack_bf16(v.x, v.y); hw.y = pack_bf16(v.z, v.w);
    lw.x = pack_bf16(v.x - bf16_rn_f32(v.x), v.y - bf16_rn_f32(v.y));
    lw.y = pack_bf16(v.z - bf16_rn_f32(v.z), v.w - bf16_rn_f32(v.w));
    reinterpret_cast<uint2*>(oh)[idx] = hw;
    reinterpret_cast<uint2*>(ol)[idx] = lw;
}

// ---------------------------------------------------------------------------
// 32x32 tiled transpose fp32 -> bf16 hi/lo
// ---------------------------------------------------------------------------
__global__ __launch_bounds__(256)
void transpose_conv_k(const float* __restrict__ in,
                      bf16* __restrict__ oh, bf16* __restrict__ ol,
                      int R, int Cc, long long sIn, long long sOut)
{
    __shared__ float t[32][33];
    in += (long long)blockIdx.z * sIn;
    const long long ob = (long long)blockIdx.z * sOut;
    const int r0 = blockIdx.y * 32, c0 = blockIdx.x * 32;
    const int tx = threadIdx.x & 31, ty = threadIdx.x >> 5;
    #pragma unroll
    for (int i = 0; i < 32; i += 8)
        t[ty + i][tx] = in[(long long)(r0 + ty + i) * Cc + c0 + tx];
    __syncthreads();
    #pragma unroll
    for (int i = 0; i < 32; i += 8) {
        float v = t[tx][ty + i];
        float h = bf16_rn_f32(v);
        long long o = ob + (long long)(c0 + ty + i) * R + r0 + tx;
        oh[o] = __float2bfloat16(v);
        ol[o] = __float2bfloat16(v - h);
    }
}

// ---------------------------------------------------------------------------
// Row softmax (rows of 4096, scale folded), writes attn as bf16 hi/lo.
// ---------------------------------------------------------------------------
__global__ __launch_bounds__(256)
void softmax2_k(const float* __restrict__ S, bf16* __restrict__ AH,
                bf16* __restrict__ AL, float scale)
{
    const float* row = S + (long long)blockIdx.x * 4096;
    const long long ob = (long long)blockIdx.x * 4096;
    const int t = threadIdx.x;
    const int base = t * 16;
    __shared__ float red[256];

    float vals[16];
    float m = -1e30f;
    #pragma unroll
    for (int i = 0; i < 4; i++) {
        float4 v = reinterpret_cast<const float4*>(row + base)[i];
        vals[i * 4 + 0] = v.x; vals[i * 4 + 1] = v.y;
        vals[i * 4 + 2] = v.z; vals[i * 4 + 3] = v.w;
    }
    #pragma unroll
    for (int i = 0; i < 16; i++) m = fmaxf(m, vals[i]);
    red[t] = m;
    __syncthreads();
    #pragma unroll
    for (int s = 128; s > 0; s >>= 1) {
        if (t < s) red[t] = fmaxf(red[t], red[t + s]);
        __syncthreads();
    }
    m = red[0];
    __syncthreads();

    float sum = 0.f;
    #pragma unroll
    for (int i = 0; i < 16; i++) {
        vals[i] = __expf(scale * (vals[i] - m));
        sum += vals[i];
    }
    red[t] = sum;
    __syncthreads();
    #pragma unroll
    for (int s = 128; s > 0; s >>= 1) {
        if (t < s) red[t] += red[t + s];
        __syncthreads();
    }
    const float inv = 1.0f / red[0];

    uint4 hw[2], lw[2];
    #pragma unroll
    for (int g = 0; g < 2; g++) {
        float v[8], l[8];
        #pragma unroll
        for (int j = 0; j < 8; j++) {
            v[j] = vals[g * 8 + j] * inv;
            l[j] = v[j] - bf16_rn_f32(v[j]);
        }
        hw[g].x = pack_bf16(v[0], v[1]); hw[g].y = pack_bf16(v[2], v[3]);
        hw[g].z = pack_bf16(v[4], v[5]); hw[g].w = pack_bf16(v[6], v[7]);
        lw[g].x = pack_bf16(l[0], l[1]); lw[g].y = pack_bf16(l[2], l[3]);
        lw[g].z = pack_bf16(l[4], l[5]); lw[g].w = pack_bf16(l[6], l[7]);
    }
    reinterpret_cast<uint4*>(AH + ob + base)[0] = hw[0];
    reinterpret_cast<uint4*>(AH + ob + base)[1] = hw[1];
    reinterpret_cast<uint4*>(AL + ob + base)[0] = lw[0];
    reinterpret_cast<uint4*>(AL + ob + base)[1] = lw[1];
}

// ---------------------------------------------------------------------------
extern "C" void kernel_launch(void* const* d_in, const int* in_sizes, int n_in,
                              void* d_out, int out_size)
{
    const float* x  = (const float*)d_in[0];
    const float* Wq = (const float*)d_in[1];
    const float* bq = (const float*)d_in[2];
    const float* Wk = (const float*)d_in[3];
    const float* bk = (const float*)d_in[4];
    const float* Wv = (const float*)d_in[5];
    const float* bv = (const float*)d_in[6];
    const float* Wo = (const float*)d_in[7];
    const float* bo = (const float*)d_in[8];
    float* out = (float*)d_out;

    const int M = NB * NSEQ;
    const float scale = 0.03125f;

    bf16 *xh, *xl, *wth, *wtl, *qh, *ql, *kh, *kl, *vth, *vtl, *ah, *al, *aoh, *aol;
    float *v, *s;
    cudaGetSymbolAddress((void**)&xh,  g_xh);  cudaGetSymbolAddress((void**)&xl,  g_xl);
    cudaGetSymbolAddress((void**)&wth, g_wth); cudaGetSymbolAddress((void**)&wtl, g_wtl);
    cudaGetSymbolAddress((void**)&qh,  g_qh);  cudaGetSymbolAddress((void**)&ql,  g_ql);
    cudaGetSymbolAddress((void**)&kh,  g_kh);  cudaGetSymbolAddress((void**)&kl,  g_kl);
    cudaGetSymbolAddress((void**)&v,   g_v);
    cudaGetSymbolAddress((void**)&vth, g_vth); cudaGetSymbolAddress((void**)&vtl, g_vtl);
    cudaGetSymbolAddress((void**)&s,   g_s);
    cudaGetSymbolAddress((void**)&ah,  g_ah);  cudaGetSymbolAddress((void**)&al,  g_al);
    cudaGetSymbolAddress((void**)&aoh, g_aoh); cudaGetSymbolAddress((void**)&aol, g_aol);

    cudaFuncSetAttribute((const void*)tc_gemm3<0, true>,  cudaFuncAttributeMaxDynamicSharedMemorySize, SMEM_BYTES);
    cudaFuncSetAttribute((const void*)tc_gemm3<0, false>, cudaFuncAttributeMaxDynamicSharedMemorySize, SMEM_BYTES);
    cudaFuncSetAttribute((const void*)tc_gemm3<1, true>,  cudaFuncAttributeMaxDynamicSharedMemorySize, SMEM_BYTES);
    cudaFuncSetAttribute((const void*)tc_gemm3<1, false>, cudaFuncAttributeMaxDynamicSharedMemorySize, SMEM_BYTES);

    const long long qkv = (long long)NSEQ * DIMC;
    const long long ss  = (long long)NSEQ * NSEQ;

    dim3 b256(256);

    // 1) split x -> xh/xl
    conv_k<<<16384, b256>>>(x, xh, xl, 4194304);

    // 2) transpose+split weights
    {
        dim3 g(32, 32, 1);
        transpose_conv_k<<<g, b256>>>(Wq, wth + 0*1048576, wtl + 0*1048576, DIMC, DIMC, 0, 0);
        transpose_conv_k<<<g, b256>>>(Wk, wth + 1*1048576, wtl + 1*1048576, DIMC, DIMC, 0, 0);
        transpose_conv_k<<<g, b256>>>(Wv, wth + 2*1048576, wtl + 2*1048576, DIMC, DIMC, 0, 0);
        transpose_conv_k<<<g, b256>>>(Wo, wth + 3*1048576, wtl + 3*1048576, DIMC, DIMC, 0, 0);
    }

    // 3) q,k (bf16 pair out) and v (fp32 out) projections
    {
        dim3 g(DIMC / BN, M / 128, 1);
        tc_gemm3<1, true><<<g, b256, SMEM_BYTES>>>(xh, xl, wth + 0*1048576, wtl + 0*1048576,
                                                   bq, nullptr, qh, ql, M, DIMC, DIMC, 0, 0, 0);
        tc_gemm3<1, true><<<g, b256, SMEM_BYTES>>>(xh, xl, wth + 1*1048576, wtl + 1*1048576,
                                                   bk, nullptr, kh, kl, M, DIMC, DIMC, 0, 0, 0);
        tc_gemm3<0, true><<<g, b256, SMEM_BYTES>>>(xh, xl, wth + 2*1048576, wtl + 2*1048576,
                                                   bv, v, nullptr, nullptr, M, DIMC, DIMC, 0, 0, 0);
    }

    // 4) vT split per batch
    {
        dim3 g(DIMC / 32, NSEQ / 32, NB);
        transpose_conv_k<<<g, b256>>>(v, vth, vtl, NSEQ, DIMC, qkv, qkv);
    }

    // 5) scores = q @ k^T (fp32 out)
    {
        dim3 g(NSEQ / BN, NSEQ / 128, NB);
        tc_gemm3<0, false><<<g, b256, SMEM_BYTES>>>(qh, ql, kh, kl, nullptr,
                                                    s, nullptr, nullptr,
                                                    NSEQ, NSEQ, DIMC, qkv, qkv, ss);
    }

    // 6) softmax -> attn bf16 pair
    softmax2_k<<<M, b256>>>(s, ah, al, scale);

    // 7) ao = attn @ vT^T (bf16 pair out), K = 4096
    {
        dim3 g(DIMC / BN, NSEQ / 128, NB);
        tc_gemm3<1, false><<<g, b256, SMEM_BYTES>>>(ah, al, vth, vtl, nullptr,
                                                    nullptr, aoh, aol,
                                                    NSEQ, DIMC, NSEQ, ss, qkv, qkv);
    }

    // 8) out = ao @ WoT^T + bo (fp32 out)
    {
        dim3 g(DIMC / BN, M / 128, 1);
        tc_gemm3<0, true><<<g, b256, SMEM_BYTES>>>(aoh, aol, wth + 3*1048576, wtl + 3*1048576,
                                                   bo, out, nullptr, nullptr,
                                                   M, DIMC, DIMC, 0, 0, 0);
    }
}

// round 12
// speedup vs baseline: 2.2524x; 1.1270x over previous
#include <cuda_runtime.h>
#include <cuda_bf16.h>
#include <cstdint>

// ---------------------------------------------------------------------------
// NaiveAttention on GB300. B=4, N=4096, C=1024 fp32.
// R12: pre-split bf16 hi/lo + 2-CTA MMA (cta_group::2, M=256 x N=256 tiles)
// + cp.async loader + 3-stage pipeline. Cuts L2 bytes/MAC by 1.5x.
// ---------------------------------------------------------------------------

#if !defined(__CUDA_ARCH__)
#define USE_TC 1
#elif defined(__CUDA_ARCH_FEAT_SM103_ALL) || defined(__CUDA_ARCH_FEAT_SM100_ALL) || \
      defined(__CUDA_ARCH_FEAT_SM101_ALL) || defined(__CUDA_ARCH_SPECIFIC__) || \
      defined(__CUDA_ARCH_FAMILY_SPECIFIC__)
#define USE_TC 1
#else
#define USE_TC 0
#endif

#define DIMC 1024
#define NSEQ 4096
#define NB   4

typedef __nv_bfloat16 bf16;

// Scratch (device globals — no allocation allowed).
__device__ bf16  g_xh [16777216], g_xl [16777216];
__device__ bf16  g_wth[4194304],  g_wtl[4194304];
__device__ bf16  g_qh [16777216], g_ql [16777216];
__device__ bf16  g_kh [16777216], g_kl [16777216];
__device__ float g_v  [16777216];
__device__ bf16  g_vth[16777216], g_vtl[16777216];
__device__ float g_s  [67108864];
__device__ bf16  g_ah [67108864], g_al [67108864];
__device__ bf16  g_aoh[16777216], g_aol[16777216];

#define KT 64
#define BN 256
// idesc kind::f16 cg2: dtype=F32(1<<4), a=b=BF16(1<<7|1<<10), N=256(32<<17), M=256(16<<24)
#define IDESC_CG2 0x10400490u
// Stage per CTA: Ahi 16K @0, Alo @16K, Bhi @32K, Blo @48K
#define BUF_BYTES 65536
#define NSTAGE 3
#define SMEM_BYTES (2048 + NSTAGE * BUF_BYTES)

// ---- bf16 helpers (legal on base target too) ------------------------------
__device__ __forceinline__ uint32_t pack_bf16(float lo, float hi) {
    uint32_t r;
    asm("cvt.rn.satfinite.bf16x2.f32 %0, %1, %2;" : "=r"(r) : "f"(hi), "f"(lo));
    return r;
}
__device__ __forceinline__ float bf16_rn_f32(float x) {
    uint32_t r;
    asm("cvt.rn.satfinite.bf16x2.f32 %0, %1, %1;" : "=r"(r) : "f"(x));
    return __uint_as_float(r << 16);
}

#if USE_TC
// ---------------------------------------------------------------------------
// sm_103a-only PTX helpers
// ---------------------------------------------------------------------------
__device__ __forceinline__ uint32_t smem_u32(const void* p) {
    uint32_t a;
    asm("{ .reg .u64 t; cvta.to.shared.u64 t, %1; cvt.u32.u64 %0, t; }"
        : "=r"(a) : "l"(p));
    return a;
}

#define MBAR_INIT(addr, cnt) \
    asm volatile("mbarrier.init.shared.b64 [%0], %1;" :: "r"(addr), "r"(cnt) : "memory")

// local wait, cta-scope acquire
#define MBAR_WAIT(addr, ph) do {                                              \
    uint32_t _m = (addr); uint32_t _p = (ph); uint32_t _done;                 \
    asm volatile("{\n\t.reg .pred p;\n\t"                                     \
        "mbarrier.try_wait.parity.acquire.cta.shared::cta.b64 p, [%1], %2;\n\t" \
        "selp.b32 %0, 1, 0, p;\n\t}"                                          \
        : "=r"(_done) : "r"(_m), "r"(_p) : "memory");                         \
    if (!_done) {                                                             \
        asm volatile("{\n\t.reg .pred P1;\n\t"                                \
            "WL_%=:\n\t"                                                      \
            "mbarrier.try_wait.parity.acquire.cta.shared::cta.b64 P1, [%0], %1, 0x989680;\n\t" \
            "@P1 bra.uni WD_%=;\n\t"                                          \
            "bra.uni WL_%=;\n\t"                                              \
            "WD_%=:\n\t}"                                                     \
            :: "r"(_m), "r"(_p) : "memory");                                  \
    }                                                                         \
} while (0)

// local wait, cluster-scope acquire (protects peer-CTA SMEM reads by cg2 MMA)
#define MBAR_WAIT_CL(addr, ph) do {                                           \
    uint32_t _m = (addr); uint32_t _p = (ph); uint32_t _done;                 \
    asm volatile("{\n\t.reg .pred p;\n\t"                                     \
        "mbarrier.try_wait.parity.acquire.cluster.shared::cta.b64 p, [%1], %2;\n\t" \
        "selp.b32 %0, 1, 0, p;\n\t}"                                          \
        : "=r"(_done) : "r"(_m), "r"(_p) : "memory");                         \
    if (!_done) {                                                             \
        asm volatile("{\n\t.reg .pred P1;\n\t"                                \
            "WL_%=:\n\t"                                                      \
            "mbarrier.try_wait.parity.acquire.cluster.shared::cta.b64 P1, [%0], %1, 0x989680;\n\t" \
            "@P1 bra.uni WD_%=;\n\t"                                          \
            "bra.uni WL_%=;\n\t"                                              \
            "WD_%=:\n\t}"                                                     \
            :: "r"(_m), "r"(_p) : "memory");                                  \
    }                                                                         \
} while (0)

// arrive on cluster-rank-0's mbarrier at the same SMEM offset (mapa)
#define MBAR_ARRIVE_R0(addr) \
    asm volatile("{\n\t.reg .b32 ra;\n\t" \
        "mapa.shared::cluster.u32 ra, %0, %1;\n\t" \
        "mbarrier.arrive.shared::cluster.b64 _, [ra];\n\t}" \
        :: "r"(addr), "r"(0) : "memory")

#define CLUSTER_SYNC() do { \
    asm volatile("barrier.cluster.arrive.aligned;" ::: "memory"); \
    asm volatile("barrier.cluster.wait.aligned;" ::: "memory"); \
} while (0)

#define TC_ALLOC_CG2(sm, n)  asm volatile("tcgen05.alloc.cta_group::2.sync.aligned.shared::cta.b32 [%0], %1;" :: "r"(sm), "r"(n) : "memory")
#define TC_DEALLOC_CG2(t, n) asm volatile("tcgen05.dealloc.cta_group::2.sync.aligned.b32 %0, %1;" :: "r"(t), "r"(n))
#define TC_RELINQ_CG2()      asm volatile("tcgen05.relinquish_alloc_permit.cta_group::2.sync.aligned;")
#define TC_COMMIT_MC2(mb)    asm volatile("tcgen05.commit.cta_group::2.mbarrier::arrive::one.shared::cluster.multicast::cluster.b64 [%0], %1;" :: "r"(mb), "h"((uint16_t)0x3) : "memory")
#define TC_FENCE_AFTER()  asm volatile("tcgen05.fence::after_thread_sync;" ::: "memory")
#define TC_FENCE_BEFORE() asm volatile("tcgen05.fence::before_thread_sync;" ::: "memory")
#define TC_WAIT_LD()      asm volatile("tcgen05.wait::ld.sync.aligned;" ::: "memory")
#define FENCE_ASYNC()     asm volatile("fence.proxy.async.shared::cta;" ::: "memory")

#define CP_ASYNC16(sm, gp) \
    asm volatile("cp.async.cg.shared.global [%0], [%1], 16;" :: "r"(sm), "l"(gp) : "memory")
#define CP_COMMIT() asm volatile("cp.async.commit_group;" ::: "memory")
#define CP_WAIT2()  asm volatile("cp.async.wait_group 2;" ::: "memory")

#define TC_LD_X32(r, a) \
    asm volatile("tcgen05.ld.sync.aligned.32x32b.x32.b32 " \
        "{%0, %1, %2, %3, %4, %5, %6, %7, %8, %9, %10, %11, %12, %13, %14, %15, " \
        " %16, %17, %18, %19, %20, %21, %22, %23, %24, %25, %26, %27, %28, %29, %30, %31}, [%32];" \
        : "=r"((r)[0]), "=r"((r)[1]), "=r"((r)[2]), "=r"((r)[3]), \
          "=r"((r)[4]), "=r"((r)[5]), "=r"((r)[6]), "=r"((r)[7]), \
          "=r"((r)[8]), "=r"((r)[9]), "=r"((r)[10]), "=r"((r)[11]), \
          "=r"((r)[12]), "=r"((r)[13]), "=r"((r)[14]), "=r"((r)[15]), \
          "=r"((r)[16]), "=r"((r)[17]), "=r"((r)[18]), "=r"((r)[19]), \
          "=r"((r)[20]), "=r"((r)[21]), "=r"((r)[22]), "=r"((r)[23]), \
          "=r"((r)[24]), "=r"((r)[25]), "=r"((r)[26]), "=r"((r)[27]), \
          "=r"((r)[28]), "=r"((r)[29]), "=r"((r)[30]), "=r"((r)[31]) \
        : "r"(a))

// cg2 bf16 SS MMA (8-register disable-output-lane vector)
__device__ __forceinline__ void mma_f16_ss_cg2(uint32_t d, uint64_t a, uint64_t b,
                                               uint32_t idesc, uint32_t en) {
    asm volatile("{\n\t.reg .pred p;\n\tsetp.ne.u32 p, %4, 0;\n\t"
        "tcgen05.mma.cta_group::2.kind::f16 [%0], %1, %2, %3, "
        "{%5, %5, %5, %5, %5, %5, %5, %5}, p;\n\t}"
        :: "r"(d), "l"(a), "l"(b), "r"(idesc), "r"(en), "r"(0u) : "memory");
}

__device__ __forceinline__ uint64_t mk_desc(uint32_t addr) {
    const uint64_t base = (uint64_t(2) << 61) | (uint64_t(1) << 46)
                        | (uint64_t(64) << 32) | (uint64_t(1) << 16);
    return base | ((uint64_t)(addr >> 4) & 0x3FFF);
}

__device__ __forceinline__ uint32_t sw128(uint32_t off) {
    return off ^ ((off >> 3) & 0x70);
}
#endif  // USE_TC

// ---------------------------------------------------------------------------
// GEMM (2-CTA clusters):  C[z] = (Ahi+Alo)[z] @ (Bhi+Blo)[z]^T (+ bias).
//   A*: [M,K] bf16 K-major, B*: [N,K] bf16 K-major.
//   Cluster pair covers 256(M) x 256(N); each CTA: its 128 M-rows of A,
//   its 128 N-rows of B. OUTM=0: Cf fp32. OUTM=1: Chi/Clo bf16 pair.
//   Grid: x = M/128 (cluster dim 2 along x), y = N/256, z = batch.
//   M % 256 == 0, N % 256 == 0, K % 64 == 0.
// ---------------------------------------------------------------------------
template <int OUTM, bool HAS_BIAS>
__global__ __launch_bounds__(256, 1) __cluster_dims__(2, 1, 1)
void tc_gemm4(const bf16* __restrict__ Ahi, const bf16* __restrict__ Alo,
              const bf16* __restrict__ Bhi, const bf16* __restrict__ Blo,
              const float* __restrict__ bias,
              float* __restrict__ Cf, bf16* __restrict__ Chi, bf16* __restrict__ Clo,
              int M, int N, int K,
              long long sA, long long sB, long long sC)
{
    extern __shared__ char smem[];

    Ahi += (long long)blockIdx.z * sA;  Alo += (long long)blockIdx.z * sA;
    Bhi += (long long)blockIdx.z * sB;  Blo += (long long)blockIdx.z * sB;

    const int tid  = threadIdx.x;
    const int rank = blockIdx.x & 1;                  // == cluster_ctarank
    const int m0   = blockIdx.x * 128;                // includes rank offset
    const int n0   = blockIdx.y * BN;                 // 256-wide N tile
    const int nb0  = n0 + rank * 128;                 // this CTA's B rows

#if USE_TC
    const uint32_t sb    = smem_u32(smem);
    const uint32_t tiles = (sb + 64 + 1023) & ~1023u;
    char* tilesg = smem + (tiles - sb);
    const uint32_t mbF[NSTAGE] = { sb,      sb + 8,  sb + 16 };  // MMA-done (both CTAs)
    const uint32_t mbR[NSTAGE] = { sb + 24, sb + 32, sb + 40 };  // loads-ready (rank0)
    const uint32_t tptr = sb + 48;

    if (tid < 32) TC_ALLOC_CG2(tptr, 256);
    if (tid == 0) {
        MBAR_INIT(mbF[0], 1); MBAR_INIT(mbF[1], 1); MBAR_INIT(mbF[2], 1);
        MBAR_INIT(mbR[0], 2); MBAR_INIT(mbR[1], 2); MBAR_INIT(mbR[2], 2);
    }
    __syncthreads();
    uint32_t tmem;
    asm volatile("ld.shared.b32 %0, [%1];" : "=r"(tmem) : "r"(tptr));

    // All mbarriers + TMEM alloc visible cluster-wide before any traffic.
    CLUSTER_SYNC();

    const int nk = K / KT;
    int phF[NSTAGE] = { 0, 0, 0 };
    int phR = 0, stR = 0;   // ready-phase tracking (rank0 tid0 only)

    // loader geometry: 2 threads per row, 64B half-rows.
    const int lrow  = tid >> 1;          // 0..127
    const int lhalf = tid & 1;
    const long long aoff = (long long)(m0 + lrow) * K + lhalf * 32;
    const long long boff = (long long)(nb0 + lrow) * K + lhalf * 32;
    const uint32_t soff  = (uint32_t)(lrow * 128 + lhalf * 64);

    auto load_tile = [&](int tt, uint32_t sbase) {
        const long long kof = (long long)tt * KT;
        const bf16* pAh = Ahi + aoff + kof;
        const bf16* pAl = Alo + aoff + kof;
        const bf16* pBh = Bhi + boff + kof;
        const bf16* pBl = Blo + boff + kof;
        #pragma unroll
        for (int j = 0; j < 4; j++)
            CP_ASYNC16(sbase + sw128(soff + j * 16), pAh + j * 8);
        #pragma unroll
        for (int j = 0; j < 4; j++)
            CP_ASYNC16(sbase + 16384 + sw128(soff + j * 16), pAl + j * 8);
        #pragma unroll
        for (int j = 0; j < 4; j++)
            CP_ASYNC16(sbase + 32768 + sw128(soff + j * 16), pBh + j * 8);
        #pragma unroll
        for (int j = 0; j < 4; j++)
            CP_ASYNC16(sbase + 49152 + sw128(soff + j * 16), pBl + j * 8);
    };

    // prologue: tiles 0,1 -> bufs 0,1
    load_tile(0, tiles);                 CP_COMMIT();
    if (nk > 1) load_tile(1, tiles + BUF_BYTES);
    CP_COMMIT();

    for (int t = 0; t < nk; t++) {
        const int buf = t % NSTAGE;
        const uint32_t sbase = tiles + buf * BUF_BYTES;

        // issue loads for t+2 into its buffer (gated by MMA-done of t-1)
        const int tp = t + NSTAGE - 1;
        if (tp < nk) {
            const int nbuf = tp % NSTAGE;
            if (tp >= NSTAGE) { MBAR_WAIT(mbF[nbuf], phF[nbuf]); phF[nbuf] ^= 1; }
            load_tile(tp, tiles + nbuf * BUF_BYTES);
        }
        CP_COMMIT();               // keep group count aligned (may be empty)
        CP_WAIT2();                // tile t's loads are complete locally
        FENCE_ASYNC();
        __syncthreads();

        // signal: this CTA's stage `buf` is ready (arrive on rank0's mbR)
        if (tid == 0) MBAR_ARRIVE_R0(mbR[buf]);

        // rank 0 thread 0: wait both CTAs ready, then issue 12 cg2 MMAs
        if (rank == 0 && tid == 0) {
            MBAR_WAIT_CL(mbR[stR], phR);
            if (++stR == NSTAGE) { stR = 0; phR ^= 1; }
            uint64_t ah = mk_desc(sbase);
            uint64_t al = mk_desc(sbase + 16384);
            uint64_t bh = mk_desc(sbase + 32768);
            uint64_t bl = mk_desc(sbase + 49152);
            #pragma unroll
            for (int kc = 0; kc < 4; kc++)
                mma_f16_ss_cg2(tmem, ah + kc * 2, bh + kc * 2, IDESC_CG2, (t | kc) != 0);
            #pragma unroll
            for (int kc = 0; kc < 4; kc++)
                mma_f16_ss_cg2(tmem, ah + kc * 2, bl + kc * 2, IDESC_CG2, 1);
            #pragma unroll
            for (int kc = 0; kc < 4; kc++)
                mma_f16_ss_cg2(tmem, al + kc * 2, bh + kc * 2, IDESC_CG2, 1);
            TC_COMMIT_MC2(mbF[buf]);   // arrives at BOTH CTAs' mbF[buf]
        }
    }

    // drain: last commit covers all previously issued MMAs
    {
        const int lastbuf = (nk - 1) % NSTAGE;
        MBAR_WAIT(mbF[lastbuf], phF[lastbuf]);
    }
    TC_FENCE_AFTER();

    if (HAS_BIAS) {
        ((float*)tilesg)[tid] = bias[n0 + tid];   // 256 floats
        __syncthreads();
    }

    // epilogue: each CTA reads its own 128 TMEM lanes x 256 cols
    if (tid < 128) {
        const int row = m0 + tid;
        const float* bsm = (const float*)tilesg;
        #pragma unroll
        for (int h = 0; h < 2; h++) {
            uint32_t d[128];
            TC_LD_X32(d +  0, tmem + h * 128 +  0);
            TC_LD_X32(d + 32, tmem + h * 128 + 32);
            TC_LD_X32(d + 64, tmem + h * 128 + 64);
            TC_LD_X32(d + 96, tmem + h * 128 + 96);
            TC_WAIT_LD();
            TC_FENCE_BEFORE();

            if (OUTM == 0) {
                float* cp = Cf + (long long)blockIdx.z * sC
                          + (long long)row * N + n0 + h * 128;
                #pragma unroll
                for (int c = 0; c < 128; c += 4) {
                    float4 o;
                    o.x = __uint_as_float(d[c + 0]);
                    o.y = __uint_as_float(d[c + 1]);
                    o.z = __uint_as_float(d[c + 2]);
                    o.w = __uint_as_float(d[c + 3]);
                    if (HAS_BIAS) {
                        o.x += bsm[h * 128 + c + 0]; o.y += bsm[h * 128 + c + 1];
                        o.z += bsm[h * 128 + c + 2]; o.w += bsm[h * 128 + c + 3];
                    }
                    *reinterpret_cast<float4*>(cp + c) = o;
                }
            } else {
                const long long rb = (long long)blockIdx.z * sC
                                   + (long long)row * N + n0 + h * 128;
                #pragma unroll
                for (int c = 0; c < 128; c += 8) {
                    float v[8];
                    #pragma unroll
                    for (int j = 0; j < 8; j++) {
                        v[j] = __uint_as_float(d[c + j]);
                        if (HAS_BIAS) v[j] += bsm[h * 128 + c + j];
                    }
                    uint4 hw, lw;
                    hw.x = pack_bf16(v[0], v[1]); hw.y = pack_bf16(v[2], v[3]);
                    hw.z = pack_bf16(v[4], v[5]); hw.w = pack_bf16(v[6], v[7]);
                    float l[8];
                    #pragma unroll
                    for (int j = 0; j < 8; j++) l[j] = v[j] - bf16_rn_f32(v[j]);
                    lw.x = pack_bf16(l[0], l[1]); lw.y = pack_bf16(l[2], l[3]);
                    lw.z = pack_bf16(l[4], l[5]); lw.w = pack_bf16(l[6], l[7]);
                    *reinterpret_cast<uint4*>(Chi + rb + c) = hw;
                    *reinterpret_cast<uint4*>(Clo + rb + c) = lw;
                }
            }
        }
    }

    __syncthreads();
    if (tid == 0) {
        asm volatile("mbarrier.inval.shared.b64 [%0];" :: "r"(mbF[0]) : "memory");
        asm volatile("mbarrier.inval.shared.b64 [%0];" :: "r"(mbF[1]) : "memory");
        asm volatile("mbarrier.inval.shared.b64 [%0];" :: "r"(mbF[2]) : "memory");
        asm volatile("mbarrier.inval.shared.b64 [%0];" :: "r"(mbR[0]) : "memory");
        asm volatile("mbarrier.inval.shared.b64 [%0];" :: "r"(mbR[1]) : "memory");
        asm volatile("mbarrier.inval.shared.b64 [%0];" :: "r"(mbR[2]) : "memory");
    }
    __syncthreads();
    if (tid < 32) { TC_RELINQ_CG2(); TC_DEALLOC_CG2(tmem, 256); }
    CLUSTER_SYNC();

#else
    // ================= SIMT fallback (base target; never selected) =========
    float (*As)[128] = reinterpret_cast<float (*)[128]>(smem);
    float (*Bs)[128] = reinterpret_cast<float (*)[128]>(smem + 4096);

    const int ty = tid >> 4, tx = tid & 15;
    const int aRow = tid >> 1, aCol = (tid & 1) * 4;

    for (int half = 0; half < 2; half++) {
        const int n0h = n0 + half * 128;
        float acc[8][8] = {};
        for (int k0 = 0; k0 < K; k0 += 8) {
            #pragma unroll
            for (int e = 0; e < 4; e++) {
                long long ia = (long long)(m0 + aRow) * K + k0 + aCol + e;
                As[aCol + e][aRow] = __bfloat162float(Ahi[ia]) + __bfloat162float(Alo[ia]);
                long long ib = (long long)(n0h + aRow) * K + k0 + aCol + e;
                Bs[aCol + e][aRow] = __bfloat162float(Bhi[ib]) + __bfloat162float(Blo[ib]);
            }
            __syncthreads();
            #pragma unroll
            for (int kk = 0; kk < 8; kk++) {
                float ra[8], rb[8];
                #pragma unroll
                for (int i = 0; i < 8; i++) ra[i] = As[kk][ty * 8 + i];
                #pragma unroll
                for (int j = 0; j < 8; j++) rb[j] = Bs[kk][tx * 8 + j];
                #pragma unroll
                for (int i = 0; i < 8; i++)
                    #pragma unroll
                    for (int j = 0; j < 8; j++)
                        acc[i][j] = fmaf(ra[i], rb[j], acc[i][j]);
            }
            __syncthreads();
        }
        #pragma unroll
        for (int i = 0; i < 8; i++) {
            const int row = m0 + ty * 8 + i;
            #pragma unroll
            for (int j = 0; j < 8; j++) {
                const int col = n0h + tx * 8 + j;
                float val = acc[i][j] + (HAS_BIAS ? bias[col] : 0.f);
                long long o = (long long)blockIdx.z * sC + (long long)row * N + col;
                if (OUTM == 0) {
                    Cf[o] = val;
                } else {
                    float hh = bf16_rn_f32(val);
                    Chi[o] = __float2bfloat16(val);
                    Clo[o] = __float2bfloat16(val - hh);
                }
            }
        }
        __syncthreads();
    }
#endif
}

// ---------------------------------------------------------------------------
// Elementwise fp32 -> bf16 hi/lo split (n4 = count of float4 groups)
// ---------------------------------------------------------------------------
__global__ __launch_bounds__(256)
void conv_k(const float* __restrict__ in, bf16* __restrict__ oh,
            bf16* __restrict__ ol, long long n4)
{
    long long idx = (long long)blockIdx.x * blockDim.x + threadIdx.x;
    if (idx >= n4) return;
    float4 v = reinterpret_cast<const float4*>(in)[idx];
    uint2 hw, lw;
    hw.x = pack_bf16(v.x, v.y); hw.y = pack_bf16(v.z, v.w);
    lw.x = pack_bf16(v.x - bf16_rn_f32(v.x), v.y - bf16_rn_f32(v.y));
    lw.y = pack_bf16(v.z - bf16_rn_f32(v.z), v.w - bf16_rn_f32(v.w));
    reinterpret_cast<uint2*>(oh)[idx] = hw;
    reinterpret_cast<uint2*>(ol)[idx] = lw;
}

// ---------------------------------------------------------------------------
// 32x32 tiled transpose fp32 -> bf16 hi/lo
// ---------------------------------------------------------------------------
__global__ __launch_bounds__(256)
void transpose_conv_k(const float* __restrict__ in,
                      bf16* __restrict__ oh, bf16* __restrict__ ol,
                      int R, int Cc, long long sIn, long long sOut)
{
    __shared__ float t[32][33];
    in += (long long)blockIdx.z * sIn;
    const long long ob = (long long)blockIdx.z * sOut;
    const int r0 = blockIdx.y * 32, c0 = blockIdx.x * 32;
    const int tx = threadIdx.x & 31, ty = threadIdx.x >> 5;
    #pragma unroll
    for (int i = 0; i < 32; i += 8)
        t[ty + i][tx] = in[(long long)(r0 + ty + i) * Cc + c0 + tx];
    __syncthreads();
    #pragma unroll
    for (int i = 0; i < 32; i += 8) {
        float v = t[tx][ty + i];
        float h = bf16_rn_f32(v);
        long long o = ob + (long long)(c0 + ty + i) * R + r0 + tx;
        oh[o] = __float2bfloat16(v);
        ol[o] = __float2bfloat16(v - h);
    }
}

// ---------------------------------------------------------------------------
// Row softmax (rows of 4096, scale folded), writes attn as bf16 hi/lo.
// ---------------------------------------------------------------------------
__global__ __launch_bounds__(256)
void softmax2_k(const float* __restrict__ S, bf16* __restrict__ AH,
                bf16* __restrict__ AL, float scale)
{
    const float* row = S + (long long)blockIdx.x * 4096;
    const long long ob = (long long)blockIdx.x * 4096;
    const int t = threadIdx.x;
    const int base = t * 16;
    __shared__ float red[256];

    float vals[16];
    float m = -1e30f;
    #pragma unroll
    for (int i = 0; i < 4; i++) {
        float4 v = reinterpret_cast<const float4*>(row + base)[i];
        vals[i * 4 + 0] = v.x; vals[i * 4 + 1] = v.y;
        vals[i * 4 + 2] = v.z; vals[i * 4 + 3] = v.w;
    }
    #pragma unroll
    for (int i = 0; i < 16; i++) m = fmaxf(m, vals[i]);
    red[t] = m;
    __syncthreads();
    #pragma unroll
    for (int s = 128; s > 0; s >>= 1) {
        if (t < s) red[t] = fmaxf(red[t], red[t + s]);
        __syncthreads();
    }
    m = red[0];
    __syncthreads();

    float sum = 0.f;
    #pragma unroll
    for (int i = 0; i < 16; i++) {
        vals[i] = __expf(scale * (vals[i] - m));
        sum += vals[i];
    }
    red[t] = sum;
    __syncthreads();
    #pragma unroll
    for (int s = 128; s > 0; s >>= 1) {
        if (t < s) red[t] += red[t + s];
        __syncthreads();
    }
    const float inv = 1.0f / red[0];

    uint4 hw[2], lw[2];
    #pragma unroll
    for (int g = 0; g < 2; g++) {
        float v[8], l[8];
        #pragma unroll
        for (int j = 0; j < 8; j++) {
            v[j] = vals[g * 8 + j] * inv;
            l[j] = v[j] - bf16_rn_f32(v[j]);
        }
        hw[g].x = pack_bf16(v[0], v[1]); hw[g].y = pack_bf16(v[2], v[3]);
        hw[g].z = pack_bf16(v[4], v[5]); hw[g].w = pack_bf16(v[6], v[7]);
        lw[g].x = pack_bf16(l[0], l[1]); lw[g].y = pack_bf16(l[2], l[3]);
        lw[g].z = pack_bf16(l[4], l[5]); lw[g].w = pack_bf16(l[6], l[7]);
    }
    reinterpret_cast<uint4*>(AH + ob + base)[0] = hw[0];
    reinterpret_cast<uint4*>(AH + ob + base)[1] = hw[1];
    reinterpret_cast<uint4*>(AL + ob + base)[0] = lw[0];
    reinterpret_cast<uint4*>(AL + ob + base)[1] = lw[1];
}

// ---------------------------------------------------------------------------
extern "C" void kernel_launch(void* const* d_in, const int* in_sizes, int n_in,
                              void* d_out, int out_size)
{
    const float* x  = (const float*)d_in[0];
    const float* Wq = (const float*)d_in[1];
    const float* bq = (const float*)d_in[2];
    const float* Wk = (const float*)d_in[3];
    const float* bk = (const float*)d_in[4];
    const float* Wv = (const float*)d_in[5];
    const float* bv = (const float*)d_in[6];
    const float* Wo = (const float*)d_in[7];
    const float* bo = (const float*)d_in[8];
    float* out = (float*)d_out;

    const int M = NB * NSEQ;
    const float scale = 0.03125f;

    bf16 *xh, *xl, *wth, *wtl, *qh, *ql, *kh, *kl, *vth, *vtl, *ah, *al, *aoh, *aol;
    float *v, *s;
    cudaGetSymbolAddress((void**)&xh,  g_xh);  cudaGetSymbolAddress((void**)&xl,  g_xl);
    cudaGetSymbolAddress((void**)&wth, g_wth); cudaGetSymbolAddress((void**)&wtl, g_wtl);
    cudaGetSymbolAddress((void**)&qh,  g_qh);  cudaGetSymbolAddress((void**)&ql,  g_ql);
    cudaGetSymbolAddress((void**)&kh,  g_kh);  cudaGetSymbolAddress((void**)&kl,  g_kl);
    cudaGetSymbolAddress((void**)&v,   g_v);
    cudaGetSymbolAddress((void**)&vth, g_vth); cudaGetSymbolAddress((void**)&vtl, g_vtl);
    cudaGetSymbolAddress((void**)&s,   g_s);
    cudaGetSymbolAddress((void**)&ah,  g_ah);  cudaGetSymbolAddress((void**)&al,  g_al);
    cudaGetSymbolAddress((void**)&aoh, g_aoh); cudaGetSymbolAddress((void**)&aol, g_aol);

    cudaFuncSetAttribute((const void*)tc_gemm4<0, true>,  cudaFuncAttributeMaxDynamicSharedMemorySize, SMEM_BYTES);
    cudaFuncSetAttribute((const void*)tc_gemm4<0, false>, cudaFuncAttributeMaxDynamicSharedMemorySize, SMEM_BYTES);
    cudaFuncSetAttribute((const void*)tc_gemm4<1, true>,  cudaFuncAttributeMaxDynamicSharedMemorySize, SMEM_BYTES);
    cudaFuncSetAttribute((const void*)tc_gemm4<1, false>, cudaFuncAttributeMaxDynamicSharedMemorySize, SMEM_BYTES);

    const long long qkv = (long long)NSEQ * DIMC;
    const long long ss  = (long long)NSEQ * NSEQ;

    dim3 b256(256);

    // 1) split x -> xh/xl
    conv_k<<<16384, b256>>>(x, xh, xl, 4194304);

    // 2) transpose+split weights
    {
        dim3 g(32, 32, 1);
        transpose_conv_k<<<g, b256>>>(Wq, wth + 0*1048576, wtl + 0*1048576, DIMC, DIMC, 0, 0);
        transpose_conv_k<<<g, b256>>>(Wk, wth + 1*1048576, wtl + 1*1048576, DIMC, DIMC, 0, 0);
        transpose_conv_k<<<g, b256>>>(Wv, wth + 2*1048576, wtl + 2*1048576, DIMC, DIMC, 0, 0);
        transpose_conv_k<<<g, b256>>>(Wo, wth + 3*1048576, wtl + 3*1048576, DIMC, DIMC, 0, 0);
    }

    // 3) q,k (bf16 pair out) and v (fp32 out) projections
    {
        dim3 g(M / 128, DIMC / BN, 1);
        tc_gemm4<1, true><<<g, b256, SMEM_BYTES>>>(xh, xl, wth + 0*1048576, wtl + 0*1048576,
                                                   bq, nullptr, qh, ql, M, DIMC, DIMC, 0, 0, 0);
        tc_gemm4<1, true><<<g, b256, SMEM_BYTES>>>(xh, xl, wth + 1*1048576, wtl + 1*1048576,
                                                   bk, nullptr, kh, kl, M, DIMC, DIMC, 0, 0, 0);
        tc_gemm4<0, true><<<g, b256, SMEM_BYTES>>>(xh, xl, wth + 2*1048576, wtl + 2*1048576,
                                                   bv, v, nullptr, nullptr, M, DIMC, DIMC, 0, 0, 0);
    }

    // 4) vT split per batch
    {
        dim3 g(DIMC / 32, NSEQ / 32, NB);
        transpose_conv_k<<<g, b256>>>(v, vth, vtl, NSEQ, DIMC, qkv, qkv);
    }

    // 5) scores = q @ k^T (fp32 out)
    {
        dim3 g(NSEQ / 128, NSEQ / BN, NB);
        tc_gemm4<0, false><<<g, b256, SMEM_BYTES>>>(qh, ql, kh, kl, nullptr,
                                                    s, nullptr, nullptr,
                                                    NSEQ, NSEQ, DIMC, qkv, qkv, ss);
    }

    // 6) softmax -> attn bf16 pair
    softmax2_k<<<M, b256>>>(s, ah, al, scale);

    // 7) ao = attn @ vT^T (bf16 pair out), K = 4096
    {
        dim3 g(NSEQ / 128, DIMC / BN, NB);
        tc_gemm4<1, false><<<g, b256, SMEM_BYTES>>>(ah, al, vth, vtl, nullptr,
                                                    nullptr, aoh, aol,
                                                    NSEQ, DIMC, NSEQ, ss, qkv, qkv);
    }

    // 8) out = ao @ WoT^T + bo (fp32 out)
    {
        dim3 g(M / 128, DIMC / BN, 1);
        tc_gemm4<0, true><<<g, b256, SMEM_BYTES>>>(aoh, aol, wth + 3*1048576, wtl + 3*1048576,
                                                   bo, out, nullptr, nullptr,
                                                   M, DIMC, DIMC, 0, 0, 0);
    }
}

// round 13
// speedup vs baseline: 2.3195x; 1.0298x over previous
#include <cuda_runtime.h>
#include <cuda_bf16.h>
#include <cstdint>

// ---------------------------------------------------------------------------
// NaiveAttention on GB300. B=4, N=4096, C=1024 fp32.
// R13: R12 (2-CTA MMA, pre-split bf16 hi/lo, cp.async 3-stage) + softmax
// FUSED into GEMM epilogues: scores epilogue emits exp() + row partials,
// AV epilogue applies 1/rowsum. No fp32 scores buffer, no softmax kernel.
// ---------------------------------------------------------------------------

#if !defined(__CUDA_ARCH__)
#define USE_TC 1
#elif defined(__CUDA_ARCH_FEAT_SM103_ALL) || defined(__CUDA_ARCH_FEAT_SM100_ALL) || \
      defined(__CUDA_ARCH_FEAT_SM101_ALL) || defined(__CUDA_ARCH_SPECIFIC__) || \
      defined(__CUDA_ARCH_FAMILY_SPECIFIC__)
#define USE_TC 1
#else
#define USE_TC 0
#endif

#define DIMC 1024
#define NSEQ 4096
#define NB   4

typedef __nv_bfloat16 bf16;

// Scratch (device globals — no allocation allowed).
__device__ bf16  g_xh [16777216], g_xl [16777216];
__device__ bf16  g_wth[4194304],  g_wtl[4194304];
__device__ bf16  g_qh [16777216], g_ql [16777216];
__device__ bf16  g_kh [16777216], g_kl [16777216];
__device__ float g_v  [16777216];
__device__ bf16  g_vth[16777216], g_vtl[16777216];
__device__ bf16  g_ah [67108864], g_al [67108864];   // exp(scores) hi/lo (unnormalized)
__device__ bf16  g_aoh[16777216], g_aol[16777216];
__device__ float g_P  [262144];                       // row partial sums [4*4096][16]
__device__ float g_rinv[16384];                       // 1/rowsum

#define KT 64
#define BN 256
// idesc kind::f16 cg2: dtype=F32(1<<4), a=b=BF16(1<<7|1<<10), N=256(32<<17), M=256(16<<24)
#define IDESC_CG2 0x10400490u
// Stage per CTA: Ahi 16K @0, Alo @16K, Bhi @32K, Blo @48K
#define BUF_BYTES 65536
#define NSTAGE 3
#define SMEM_BYTES (2048 + NSTAGE * BUF_BYTES)

// ---- bf16 helpers (legal on base target too) ------------------------------
__device__ __forceinline__ uint32_t pack_bf16(float lo, float hi) {
    uint32_t r;
    asm("cvt.rn.satfinite.bf16x2.f32 %0, %1, %2;" : "=r"(r) : "f"(hi), "f"(lo));
    return r;
}
__device__ __forceinline__ float bf16_rn_f32(float x) {
    uint32_t r;
    asm("cvt.rn.satfinite.bf16x2.f32 %0, %1, %1;" : "=r"(r) : "f"(x));
    return __uint_as_float(r << 16);
}

#if USE_TC
// ---------------------------------------------------------------------------
// sm_103a-only PTX helpers
// ---------------------------------------------------------------------------
__device__ __forceinline__ uint32_t smem_u32(const void* p) {
    uint32_t a;
    asm("{ .reg .u64 t; cvta.to.shared.u64 t, %1; cvt.u32.u64 %0, t; }"
        : "=r"(a) : "l"(p));
    return a;
}

#define MBAR_INIT(addr, cnt) \
    asm volatile("mbarrier.init.shared.b64 [%0], %1;" :: "r"(addr), "r"(cnt) : "memory")

// local wait, cta-scope acquire
#define MBAR_WAIT(addr, ph) do {                                              \
    uint32_t _m = (addr); uint32_t _p = (ph); uint32_t _done;                 \
    asm volatile("{\n\t.reg .pred p;\n\t"                                     \
        "mbarrier.try_wait.parity.acquire.cta.shared::cta.b64 p, [%1], %2;\n\t" \
        "selp.b32 %0, 1, 0, p;\n\t}"                                          \
        : "=r"(_done) : "r"(_m), "r"(_p) : "memory");                         \
    if (!_done) {                                                             \
        asm volatile("{\n\t.reg .pred P1;\n\t"                                \
            "WL_%=:\n\t"                                                      \
            "mbarrier.try_wait.parity.acquire.cta.shared::cta.b64 P1, [%0], %1, 0x989680;\n\t" \
            "@P1 bra.uni WD_%=;\n\t"                                          \
            "bra.uni WL_%=;\n\t"                                              \
            "WD_%=:\n\t}"                                                     \
            :: "r"(_m), "r"(_p) : "memory");                                  \
    }                                                                         \
} while (0)

// local wait, cluster-scope acquire (protects peer-CTA SMEM reads by cg2 MMA)
#define MBAR_WAIT_CL(addr, ph) do {                                           \
    uint32_t _m = (addr); uint32_t _p = (ph); uint32_t _done;                 \
    asm volatile("{\n\t.reg .pred p;\n\t"                                     \
        "mbarrier.try_wait.parity.acquire.cluster.shared::cta.b64 p, [%1], %2;\n\t" \
        "selp.b32 %0, 1, 0, p;\n\t}"                                          \
        : "=r"(_done) : "r"(_m), "r"(_p) : "memory");                         \
    if (!_done) {                                                             \
        asm volatile("{\n\t.reg .pred P1;\n\t"                                \
            "WL_%=:\n\t"                                                      \
            "mbarrier.try_wait.parity.acquire.cluster.shared::cta.b64 P1, [%0], %1, 0x989680;\n\t" \
            "@P1 bra.uni WD_%=;\n\t"                                          \
            "bra.uni WL_%=;\n\t"                                              \
            "WD_%=:\n\t}"                                                     \
            :: "r"(_m), "r"(_p) : "memory");                                  \
    }                                                                         \
} while (0)

// arrive on cluster-rank-0's mbarrier at the same SMEM offset (mapa)
#define MBAR_ARRIVE_R0(addr) \
    asm volatile("{\n\t.reg .b32 ra;\n\t" \
        "mapa.shared::cluster.u32 ra, %0, %1;\n\t" \
        "mbarrier.arrive.shared::cluster.b64 _, [ra];\n\t}" \
        :: "r"(addr), "r"(0) : "memory")

#define CLUSTER_SYNC() do { \
    asm volatile("barrier.cluster.arrive.aligned;" ::: "memory"); \
    asm volatile("barrier.cluster.wait.aligned;" ::: "memory"); \
} while (0)

#define TC_ALLOC_CG2(sm, n)  asm volatile("tcgen05.alloc.cta_group::2.sync.aligned.shared::cta.b32 [%0], %1;" :: "r"(sm), "r"(n) : "memory")
#define TC_DEALLOC_CG2(t, n) asm volatile("tcgen05.dealloc.cta_group::2.sync.aligned.b32 %0, %1;" :: "r"(t), "r"(n))
#define TC_RELINQ_CG2()      asm volatile("tcgen05.relinquish_alloc_permit.cta_group::2.sync.aligned;")
#define TC_COMMIT_MC2(mb)    asm volatile("tcgen05.commit.cta_group::2.mbarrier::arrive::one.shared::cluster.multicast::cluster.b64 [%0], %1;" :: "r"(mb), "h"((uint16_t)0x3) : "memory")
#define TC_FENCE_AFTER()  asm volatile("tcgen05.fence::after_thread_sync;" ::: "memory")
#define TC_FENCE_BEFORE() asm volatile("tcgen05.fence::before_thread_sync;" ::: "memory")
#define TC_WAIT_LD()      asm volatile("tcgen05.wait::ld.sync.aligned;" ::: "memory")
#define FENCE_ASYNC()     asm volatile("fence.proxy.async.shared::cta;" ::: "memory")

#define CP_ASYNC16(sm, gp) \
    asm volatile("cp.async.cg.shared.global [%0], [%1], 16;" :: "r"(sm), "l"(gp) : "memory")
#define CP_COMMIT() asm volatile("cp.async.commit_group;" ::: "memory")
#define CP_WAIT2()  asm volatile("cp.async.wait_group 2;" ::: "memory")

#define TC_LD_X32(r, a) \
    asm volatile("tcgen05.ld.sync.aligned.32x32b.x32.b32 " \
        "{%0, %1, %2, %3, %4, %5, %6, %7, %8, %9, %10, %11, %12, %13, %14, %15, " \
        " %16, %17, %18, %19, %20, %21, %22, %23, %24, %25, %26, %27, %28, %29, %30, %31}, [%32];" \
        : "=r"((r)[0]), "=r"((r)[1]), "=r"((r)[2]), "=r"((r)[3]), \
          "=r"((r)[4]), "=r"((r)[5]), "=r"((r)[6]), "=r"((r)[7]), \
          "=r"((r)[8]), "=r"((r)[9]), "=r"((r)[10]), "=r"((r)[11]), \
          "=r"((r)[12]), "=r"((r)[13]), "=r"((r)[14]), "=r"((r)[15]), \
          "=r"((r)[16]), "=r"((r)[17]), "=r"((r)[18]), "=r"((r)[19]), \
          "=r"((r)[20]), "=r"((r)[21]), "=r"((r)[22]), "=r"((r)[23]), \
          "=r"((r)[24]), "=r"((r)[25]), "=r"((r)[26]), "=r"((r)[27]), \
          "=r"((r)[28]), "=r"((r)[29]), "=r"((r)[30]), "=r"((r)[31]) \
        : "r"(a))

// cg2 bf16 SS MMA (8-register disable-output-lane vector)
__device__ __forceinline__ void mma_f16_ss_cg2(uint32_t d, uint64_t a, uint64_t b,
                                               uint32_t idesc, uint32_t en) {
    asm volatile("{\n\t.reg .pred p;\n\tsetp.ne.u32 p, %4, 0;\n\t"
        "tcgen05.mma.cta_group::2.kind::f16 [%0], %1, %2, %3, "
        "{%5, %5, %5, %5, %5, %5, %5, %5}, p;\n\t}"
        :: "r"(d), "l"(a), "l"(b), "r"(idesc), "r"(en), "r"(0u) : "memory");
}

__device__ __forceinline__ uint64_t mk_desc(uint32_t addr) {
    const uint64_t base = (uint64_t(2) << 61) | (uint64_t(1) << 46)
                        | (uint64_t(64) << 32) | (uint64_t(1) << 16);
    return base | ((uint64_t)(addr >> 4) & 0x3FFF);
}

__device__ __forceinline__ uint32_t sw128(uint32_t off) {
    return off ^ ((off >> 3) & 0x70);
}
#endif  // USE_TC

// ---------------------------------------------------------------------------
// GEMM (2-CTA clusters):  C[z] = (Ahi+Alo)[z] @ (Bhi+Blo)[z]^T.
//   OUTM=0: Cf fp32 (+bias).
//   OUTM=1: Chi/Clo bf16 pair (+bias).
//   OUTM=2: e = exp(escale*acc) -> Chi/Clo pair; per-row partials to Prow.
//   OUTM=3: acc * rinv[row]     -> Chi/Clo pair.
//   Cluster pair covers 256(M) x 256(N). Grid: x=M/128 (cluster dim 2),
//   y=N/256, z=batch. M%256==0, N%256==0, K%64==0.
// ---------------------------------------------------------------------------
template <int OUTM, bool HAS_BIAS>
__global__ __launch_bounds__(256, 1) __cluster_dims__(2, 1, 1)
void tc_gemm4(const bf16* __restrict__ Ahi, const bf16* __restrict__ Alo,
              const bf16* __restrict__ Bhi, const bf16* __restrict__ Blo,
              const float* __restrict__ bias,
              float* __restrict__ Cf, bf16* __restrict__ Chi, bf16* __restrict__ Clo,
              const float* __restrict__ rinv, float* __restrict__ Prow, float escale,
              int M, int N, int K,
              long long sA, long long sB, long long sC)
{
    extern __shared__ char smem[];

    Ahi += (long long)blockIdx.z * sA;  Alo += (long long)blockIdx.z * sA;
    Bhi += (long long)blockIdx.z * sB;  Blo += (long long)blockIdx.z * sB;

    const int tid  = threadIdx.x;
    const int rank = blockIdx.x & 1;                  // == cluster_ctarank
    const int m0   = blockIdx.x * 128;                // includes rank offset
    const int n0   = blockIdx.y * BN;                 // 256-wide N tile
    const int nb0  = n0 + rank * 128;                 // this CTA's B rows

#if USE_TC
    const uint32_t sb    = smem_u32(smem);
    const uint32_t tiles = (sb + 64 + 1023) & ~1023u;
    char* tilesg = smem + (tiles - sb);
    const uint32_t mbF[NSTAGE] = { sb,      sb + 8,  sb + 16 };  // MMA-done (both CTAs)
    const uint32_t mbR[NSTAGE] = { sb + 24, sb + 32, sb + 40 };  // loads-ready (rank0)
    const uint32_t tptr = sb + 48;

    if (tid < 32) TC_ALLOC_CG2(tptr, 256);
    if (tid == 0) {
        MBAR_INIT(mbF[0], 1); MBAR_INIT(mbF[1], 1); MBAR_INIT(mbF[2], 1);
        MBAR_INIT(mbR[0], 2); MBAR_INIT(mbR[1], 2); MBAR_INIT(mbR[2], 2);
    }
    __syncthreads();
    uint32_t tmem;
    asm volatile("ld.shared.b32 %0, [%1];" : "=r"(tmem) : "r"(tptr));

    // All mbarriers + TMEM alloc visible cluster-wide before any traffic.
    CLUSTER_SYNC();

    const int nk = K / KT;
    int phF[NSTAGE] = { 0, 0, 0 };
    int phR = 0, stR = 0;   // ready-phase tracking (rank0 tid0 only)

    // loader geometry: 2 threads per row, 64B half-rows.
    const int lrow  = tid >> 1;          // 0..127
    const int lhalf = tid & 1;
    const long long aoff = (long long)(m0 + lrow) * K + lhalf * 32;
    const long long boff = (long long)(nb0 + lrow) * K + lhalf * 32;
    const uint32_t soff  = (uint32_t)(lrow * 128 + lhalf * 64);

    auto load_tile = [&](int tt, uint32_t sbase) {
        const long long kof = (long long)tt * KT;
        const bf16* pAh = Ahi + aoff + kof;
        const bf16* pAl = Alo + aoff + kof;
        const bf16* pBh = Bhi + boff + kof;
        const bf16* pBl = Blo + boff + kof;
        #pragma unroll
        for (int j = 0; j < 4; j++)
            CP_ASYNC16(sbase + sw128(soff + j * 16), pAh + j * 8);
        #pragma unroll
        for (int j = 0; j < 4; j++)
            CP_ASYNC16(sbase + 16384 + sw128(soff + j * 16), pAl + j * 8);
        #pragma unroll
        for (int j = 0; j < 4; j++)
            CP_ASYNC16(sbase + 32768 + sw128(soff + j * 16), pBh + j * 8);
        #pragma unroll
        for (int j = 0; j < 4; j++)
            CP_ASYNC16(sbase + 49152 + sw128(soff + j * 16), pBl + j * 8);
    };

    // prologue: tiles 0,1 -> bufs 0,1
    load_tile(0, tiles);                 CP_COMMIT();
    if (nk > 1) load_tile(1, tiles + BUF_BYTES);
    CP_COMMIT();

    for (int t = 0; t < nk; t++) {
        const int buf = t % NSTAGE;
        const uint32_t sbase = tiles + buf * BUF_BYTES;

        // issue loads for t+2 into its buffer (gated by MMA-done of t-1)
        const int tp = t + NSTAGE - 1;
        if (tp < nk) {
            const int nbuf = tp % NSTAGE;
            if (tp >= NSTAGE) { MBAR_WAIT(mbF[nbuf], phF[nbuf]); phF[nbuf] ^= 1; }
            load_tile(tp, tiles + nbuf * BUF_BYTES);
        }
        CP_COMMIT();               // keep group count aligned (may be empty)
        CP_WAIT2();                // tile t's loads are complete locally
        FENCE_ASYNC();
        __syncthreads();

        // signal: this CTA's stage `buf` is ready (arrive on rank0's mbR)
        if (tid == 0) MBAR_ARRIVE_R0(mbR[buf]);

        // rank 0 thread 0: wait both CTAs ready, then issue 12 cg2 MMAs
        if (rank == 0 && tid == 0) {
            MBAR_WAIT_CL(mbR[stR], phR);
            if (++stR == NSTAGE) { stR = 0; phR ^= 1; }
            uint64_t ah = mk_desc(sbase);
            uint64_t al = mk_desc(sbase + 16384);
            uint64_t bh = mk_desc(sbase + 32768);
            uint64_t bl = mk_desc(sbase + 49152);
            #pragma unroll
            for (int kc = 0; kc < 4; kc++)
                mma_f16_ss_cg2(tmem, ah + kc * 2, bh + kc * 2, IDESC_CG2, (t | kc) != 0);
            #pragma unroll
            for (int kc = 0; kc < 4; kc++)
                mma_f16_ss_cg2(tmem, ah + kc * 2, bl + kc * 2, IDESC_CG2, 1);
            #pragma unroll
            for (int kc = 0; kc < 4; kc++)
                mma_f16_ss_cg2(tmem, al + kc * 2, bh + kc * 2, IDESC_CG2, 1);
            TC_COMMIT_MC2(mbF[buf]);   // arrives at BOTH CTAs' mbF[buf]
        }
    }

    // drain: last commit covers all previously issued MMAs
    {
        const int lastbuf = (nk - 1) % NSTAGE;
        MBAR_WAIT(mbF[lastbuf], phF[lastbuf]);
    }
    TC_FENCE_AFTER();

    if (HAS_BIAS) {
        ((float*)tilesg)[tid] = bias[n0 + tid];   // 256 floats
        __syncthreads();
    }

    // epilogue: each CTA reads its own 128 TMEM lanes x 256 cols
    if (tid < 128) {
        const int row = m0 + tid;
        const float* bsm = (const float*)tilesg;
        float rsum = 0.f;
        float rscale = 1.f;
        if (OUTM == 3) rscale = rinv[(long long)blockIdx.z * M + row];

        #pragma unroll
        for (int h = 0; h < 2; h++) {
            uint32_t d[128];
            TC_LD_X32(d +  0, tmem + h * 128 +  0);
            TC_LD_X32(d + 32, tmem + h * 128 + 32);
            TC_LD_X32(d + 64, tmem + h * 128 + 64);
            TC_LD_X32(d + 96, tmem + h * 128 + 96);
            TC_WAIT_LD();
            TC_FENCE_BEFORE();

            if (OUTM == 0) {
                float* cp = Cf + (long long)blockIdx.z * sC
                          + (long long)row * N + n0 + h * 128;
                #pragma unroll
                for (int c = 0; c < 128; c += 4) {
                    float4 o;
                    o.x = __uint_as_float(d[c + 0]);
                    o.y = __uint_as_float(d[c + 1]);
                    o.z = __uint_as_float(d[c + 2]);
                    o.w = __uint_as_float(d[c + 3]);
                    if (HAS_BIAS) {
                        o.x += bsm[h * 128 + c + 0]; o.y += bsm[h * 128 + c + 1];
                        o.z += bsm[h * 128 + c + 2]; o.w += bsm[h * 128 + c + 3];
                    }
                    *reinterpret_cast<float4*>(cp + c) = o;
                }
            } else {
                const long long rb = (long long)blockIdx.z * sC
                                   + (long long)row * N + n0 + h * 128;
                #pragma unroll
                for (int c = 0; c < 128; c += 8) {
                    float v[8];
                    #pragma unroll
                    for (int j = 0; j < 8; j++) {
                        v[j] = __uint_as_float(d[c + j]);
                        if (HAS_BIAS) v[j] += bsm[h * 128 + c + j];
                        if (OUTM == 2) { v[j] = __expf(escale * v[j]); rsum += v[j]; }
                        if (OUTM == 3) v[j] *= rscale;
                    }
                    uint4 hw, lw;
                    hw.x = pack_bf16(v[0], v[1]); hw.y = pack_bf16(v[2], v[3]);
                    hw.z = pack_bf16(v[4], v[5]); hw.w = pack_bf16(v[6], v[7]);
                    float l[8];
                    #pragma unroll
                    for (int j = 0; j < 8; j++) l[j] = v[j] - bf16_rn_f32(v[j]);
                    lw.x = pack_bf16(l[0], l[1]); lw.y = pack_bf16(l[2], l[3]);
                    lw.z = pack_bf16(l[4], l[5]); lw.w = pack_bf16(l[6], l[7]);
                    *reinterpret_cast<uint4*>(Chi + rb + c) = hw;
                    *reinterpret_cast<uint4*>(Clo + rb + c) = lw;
                }
            }
        }
        if (OUTM == 2)
            Prow[((long long)blockIdx.z * M + row) * (N >> 8) + blockIdx.y] = rsum;
    }

    __syncthreads();
    if (tid == 0) {
        asm volatile("mbarrier.inval.shared.b64 [%0];" :: "r"(mbF[0]) : "memory");
        asm volatile("mbarrier.inval.shared.b64 [%0];" :: "r"(mbF[1]) : "memory");
        asm volatile("mbarrier.inval.shared.b64 [%0];" :: "r"(mbF[2]) : "memory");
        asm volatile("mbarrier.inval.shared.b64 [%0];" :: "r"(mbR[0]) : "memory");
        asm volatile("mbarrier.inval.shared.b64 [%0];" :: "r"(mbR[1]) : "memory");
        asm volatile("mbarrier.inval.shared.b64 [%0];" :: "r"(mbR[2]) : "memory");
    }
    __syncthreads();
    if (tid < 32) { TC_RELINQ_CG2(); TC_DEALLOC_CG2(tmem, 256); }
    CLUSTER_SYNC();

#else
    // ================= SIMT fallback (base target; never selected) =========
    float (*As)[128] = reinterpret_cast<float (*)[128]>(smem);
    float (*Bs)[128] = reinterpret_cast<float (*)[128]>(smem + 4096);

    const int ty = tid >> 4, tx = tid & 15;
    const int aRow = tid >> 1, aCol = (tid & 1) * 4;

    for (int half = 0; half < 2; half++) {
        const int n0h = n0 + half * 128;
        float acc[8][8] = {};
        for (int k0 = 0; k0 < K; k0 += 8) {
            #pragma unroll
            for (int e = 0; e < 4; e++) {
                long long ia = (long long)(m0 + aRow) * K + k0 + aCol + e;
                As[aCol + e][aRow] = __bfloat162float(Ahi[ia]) + __bfloat162float(Alo[ia]);
                long long ib = (long long)(n0h + aRow) * K + k0 + aCol + e;
                Bs[aCol + e][aRow] = __bfloat162float(Bhi[ib]) + __bfloat162float(Blo[ib]);
            }
            __syncthreads();
            #pragma unroll
            for (int kk = 0; kk < 8; kk++) {
                float ra[8], rb[8];
                #pragma unroll
                for (int i = 0; i < 8; i++) ra[i] = As[kk][ty * 8 + i];
                #pragma unroll
                for (int j = 0; j < 8; j++) rb[j] = Bs[kk][tx * 8 + j];
                #pragma unroll
                for (int i = 0; i < 8; i++)
                    #pragma unroll
                    for (int j = 0; j < 8; j++)
                        acc[i][j] = fmaf(ra[i], rb[j], acc[i][j]);
            }
            __syncthreads();
        }
        #pragma unroll
        for (int i = 0; i < 8; i++) {
            const int row = m0 + ty * 8 + i;
            float psum = 0.f;
            #pragma unroll
            for (int j = 0; j < 8; j++) {
                const int col = n0h + tx * 8 + j;
                float val = acc[i][j] + (HAS_BIAS ? bias[col] : 0.f);
                if (OUTM == 2) { val = __expf(escale * val); psum += val; }
                if (OUTM == 3) val *= rinv[(long long)blockIdx.z * M + row];
                long long o = (long long)blockIdx.z * sC + (long long)row * N + col;
                if (OUTM == 0) {
                    Cf[o] = val;
                } else {
                    float hh = bf16_rn_f32(val);
                    Chi[o] = __float2bfloat16(val);
                    Clo[o] = __float2bfloat16(val - hh);
                }
            }
            if (OUTM == 2)
                atomicAdd(&Prow[((long long)blockIdx.z * M + row) * (N >> 8) + blockIdx.y], psum);
        }
        __syncthreads();
    }
#endif
}

// ---------------------------------------------------------------------------
// rowinv: rinv[i] = 1 / sum_t P[i][t]   (i over NB*NSEQ rows, ntile partials)
// ---------------------------------------------------------------------------
__global__ __launch_bounds__(256)
void rowinv_k(const float* __restrict__ P, float* __restrict__ rinv, int ntile)
{
    int i = blockIdx.x * blockDim.x + threadIdx.x;
    if (i >= NB * NSEQ) return;
    const float* p = P + (long long)i * ntile;
    float s = 0.f;
    for (int t = 0; t < ntile; t++) s += p[t];
    rinv[i] = 1.0f / s;
}

// ---------------------------------------------------------------------------
// Elementwise fp32 -> bf16 hi/lo split (n4 = count of float4 groups)
// ---------------------------------------------------------------------------
__global__ __launch_bounds__(256)
void conv_k(const float* __restrict__ in, bf16* __restrict__ oh,
            bf16* __restrict__ ol, long long n4)
{
    long long idx = (long long)blockIdx.x * blockDim.x + threadIdx.x;
    if (idx >= n4) return;
    float4 v = reinterpret_cast<const float4*>(in)[idx];
    uint2 hw, lw;
    hw.x = pack_bf16(v.x, v.y); hw.y = pack_bf16(v.z, v.w);
    lw.x = pack_bf16(v.x - bf16_rn_f32(v.x), v.y - bf16_rn_f32(v.y));
    lw.y = pack_bf16(v.z - bf16_rn_f32(v.z), v.w - bf16_rn_f32(v.w));
    reinterpret_cast<uint2*>(oh)[idx] = hw;
    reinterpret_cast<uint2*>(ol)[idx] = lw;
}

// ---------------------------------------------------------------------------
// 32x32 tiled transpose fp32 -> bf16 hi/lo
// ---------------------------------------------------------------------------
__global__ __launch_bounds__(256)
void transpose_conv_k(const float* __restrict__ in,
                      bf16* __restrict__ oh, bf16* __restrict__ ol,
                      int R, int Cc, long long sIn, long long sOut)
{
    __shared__ float t[32][33];
    in += (long long)blockIdx.z * sIn;
    const long long ob = (long long)blockIdx.z * sOut;
    const int r0 = blockIdx.y * 32, c0 = blockIdx.x * 32;
    const int tx = threadIdx.x & 31, ty = threadIdx.x >> 5;
    #pragma unroll
    for (int i = 0; i < 32; i += 8)
        t[ty + i][tx] = in[(long long)(r0 + ty + i) * Cc + c0 + tx];
    __syncthreads();
    #pragma unroll
    for (int i = 0; i < 32; i += 8) {
        float v = t[tx][ty + i];
        float h = bf16_rn_f32(v);
        long long o = ob + (long long)(c0 + ty + i) * R + r0 + tx;
        oh[o] = __float2bfloat16(v);
        ol[o] = __float2bfloat16(v - h);
    }
}

// ---------------------------------------------------------------------------
extern "C" void kernel_launch(void* const* d_in, const int* in_sizes, int n_in,
                              void* d_out, int out_size)
{
    const float* x  = (const float*)d_in[0];
    const float* Wq = (const float*)d_in[1];
    const float* bq = (const float*)d_in[2];
    const float* Wk = (const float*)d_in[3];
    const float* bk = (const float*)d_in[4];
    const float* Wv = (const float*)d_in[5];
    const float* bv = (const float*)d_in[6];
    const float* Wo = (const float*)d_in[7];
    const float* bo = (const float*)d_in[8];
    float* out = (float*)d_out;

    const int M = NB * NSEQ;
    const float scale = 0.03125f;

    bf16 *xh, *xl, *wth, *wtl, *qh, *ql, *kh, *kl, *vth, *vtl, *ah, *al, *aoh, *aol;
    float *v, *P, *rinv;
    cudaGetSymbolAddress((void**)&xh,  g_xh);  cudaGetSymbolAddress((void**)&xl,  g_xl);
    cudaGetSymbolAddress((void**)&wth, g_wth); cudaGetSymbolAddress((void**)&wtl, g_wtl);
    cudaGetSymbolAddress((void**)&qh,  g_qh);  cudaGetSymbolAddress((void**)&ql,  g_ql);
    cudaGetSymbolAddress((void**)&kh,  g_kh);  cudaGetSymbolAddress((void**)&kl,  g_kl);
    cudaGetSymbolAddress((void**)&v,   g_v);
    cudaGetSymbolAddress((void**)&vth, g_vth); cudaGetSymbolAddress((void**)&vtl, g_vtl);
    cudaGetSymbolAddress((void**)&ah,  g_ah);  cudaGetSymbolAddress((void**)&al,  g_al);
    cudaGetSymbolAddress((void**)&aoh, g_aoh); cudaGetSymbolAddress((void**)&aol, g_aol);
    cudaGetSymbolAddress((void**)&P,   g_P);   cudaGetSymbolAddress((void**)&rinv, g_rinv);

    cudaFuncSetAttribute((const void*)tc_gemm4<0, true>,  cudaFuncAttributeMaxDynamicSharedMemorySize, SMEM_BYTES);
    cudaFuncSetAttribute((const void*)tc_gemm4<1, true>,  cudaFuncAttributeMaxDynamicSharedMemorySize, SMEM_BYTES);
    cudaFuncSetAttribute((const void*)tc_gemm4<2, false>, cudaFuncAttributeMaxDynamicSharedMemorySize, SMEM_BYTES);
    cudaFuncSetAttribute((const void*)tc_gemm4<3, false>, cudaFuncAttributeMaxDynamicSharedMemorySize, SMEM_BYTES);

    const long long qkv = (long long)NSEQ * DIMC;
    const long long ss  = (long long)NSEQ * NSEQ;

    dim3 b256(256);

    // 1) split x -> xh/xl
    conv_k<<<16384, b256>>>(x, xh, xl, 4194304);

    // 2) transpose+split weights
    {
        dim3 g(32, 32, 1);
        transpose_conv_k<<<g, b256>>>(Wq, wth + 0*1048576, wtl + 0*1048576, DIMC, DIMC, 0, 0);
        transpose_conv_k<<<g, b256>>>(Wk, wth + 1*1048576, wtl + 1*1048576, DIMC, DIMC, 0, 0);
        transpose_conv_k<<<g, b256>>>(Wv, wth + 2*1048576, wtl + 2*1048576, DIMC, DIMC, 0, 0);
        transpose_conv_k<<<g, b256>>>(Wo, wth + 3*1048576, wtl + 3*1048576, DIMC, DIMC, 0, 0);
    }

    // 3) q,k (bf16 pair out) and v (fp32 out) projections
    {
        dim3 g(M / 128, DIMC / BN, 1);
        tc_gemm4<1, true><<<g, b256, SMEM_BYTES>>>(xh, xl, wth + 0*1048576, wtl + 0*1048576,
                                                   bq, nullptr, qh, ql, nullptr, nullptr, 0.f,
                                                   M, DIMC, DIMC, 0, 0, 0);
        tc_gemm4<1, true><<<g, b256, SMEM_BYTES>>>(xh, xl, wth + 1*1048576, wtl + 1*1048576,
                                                   bk, nullptr, kh, kl, nullptr, nullptr, 0.f,
                                                   M, DIMC, DIMC, 0, 0, 0);
        tc_gemm4<0, true><<<g, b256, SMEM_BYTES>>>(xh, xl, wth + 2*1048576, wtl + 2*1048576,
                                                   bv, v, nullptr, nullptr, nullptr, nullptr, 0.f,
                                                   M, DIMC, DIMC, 0, 0, 0);
    }

    // 4) vT split per batch
    {
        dim3 g(DIMC / 32, NSEQ / 32, NB);
        transpose_conv_k<<<g, b256>>>(v, vth, vtl, NSEQ, DIMC, qkv, qkv);
    }

    // 5) e = exp(scale * q@k^T)  -> ah/al (unnormalized) + row partials
    {
        dim3 g(NSEQ / 128, NSEQ / BN, NB);
        tc_gemm4<2, false><<<g, b256, SMEM_BYTES>>>(qh, ql, kh, kl, nullptr,
                                                    nullptr, ah, al, nullptr, P, scale,
                                                    NSEQ, NSEQ, DIMC, qkv, qkv, ss);
    }

    // 6) rinv = 1/rowsum
    rowinv_k<<<64, b256>>>(P, rinv, NSEQ / BN);

    // 7) ao = (e @ vT^T) * rinv  (bf16 pair out), K = 4096
    {
        dim3 g(NSEQ / 128, DIMC / BN, NB);
        tc_gemm4<3, false><<<g, b256, SMEM_BYTES>>>(ah, al, vth, vtl, nullptr,
                                                    nullptr, aoh, aol, rinv, nullptr, 0.f,
                                                    NSEQ, DIMC, NSEQ, ss, qkv, qkv);
    }

    // 8) out = ao @ WoT^T + bo (fp32 out)
    {
        dim3 g(M / 128, DIMC / BN, 1);
        tc_gemm4<0, true><<<g, b256, SMEM_BYTES>>>(aoh, aol, wth + 3*1048576, wtl + 3*1048576,
                                                   bo, out, nullptr, nullptr, nullptr, nullptr, 0.f,
                                                   M, DIMC, DIMC, 0, 0, 0);
    }
}

// round 14
// speedup vs baseline: 2.7630x; 1.1912x over previous
#include <cuda_runtime.h>
#include <cuda_bf16.h>
#include <cstdint>

// ---------------------------------------------------------------------------
// NaiveAttention on GB300. B=4, N=4096, C=1024 fp32.
// R14: 2-CTA MMA clusters computing 256(M) x 512(N) tiles (two N=256 halves,
// TMEM D0/D1), pre-split bf16 hi/lo, cp.async 2-stage pipeline, fused softmax.
// 25% less L2 traffic per MAC -> loads drop below the LTS cap.
// ---------------------------------------------------------------------------

#if !defined(__CUDA_ARCH__)
#define USE_TC 1
#elif defined(__CUDA_ARCH_FEAT_SM103_ALL) || defined(__CUDA_ARCH_FEAT_SM100_ALL) || \
      defined(__CUDA_ARCH_FEAT_SM101_ALL) || defined(__CUDA_ARCH_SPECIFIC__) || \
      defined(__CUDA_ARCH_FAMILY_SPECIFIC__)
#define USE_TC 1
#else
#define USE_TC 0
#endif

#define DIMC 1024
#define NSEQ 4096
#define NB   4

typedef __nv_bfloat16 bf16;

// Scratch (device globals — no allocation allowed).
__device__ bf16  g_xh [16777216], g_xl [16777216];
__device__ bf16  g_wth[4194304],  g_wtl[4194304];
__device__ bf16  g_qh [16777216], g_ql [16777216];
__device__ bf16  g_kh [16777216], g_kl [16777216];
__device__ float g_v  [16777216];
__device__ bf16  g_vth[16777216], g_vtl[16777216];
__device__ bf16  g_ah [67108864], g_al [67108864];   // exp(scores) hi/lo (unnormalized)
__device__ bf16  g_aoh[16777216], g_aol[16777216];
__device__ float g_P  [262144];                       // row partial sums
__device__ float g_rinv[16384];                       // 1/rowsum

#define KT 64
#define BNC 512      // cluster N tile (two 256 halves)
// idesc kind::f16 cg2: dtype=F32(1<<4), a=b=BF16(1<<7|1<<10), N=256(32<<17), M=256(16<<24)
#define IDESC_CG2 0x10400490u
// Stage per CTA: Ahi16K@0 Alo@16K | B0hi@32K B0lo@48K | B1hi@64K B1lo@80K
#define BUF_BYTES 98304
#define NSTAGE 2
#define SMEM_BYTES (2048 + NSTAGE * BUF_BYTES)

// ---- bf16 helpers (legal on base target too) ------------------------------
__device__ __forceinline__ uint32_t pack_bf16(float lo, float hi) {
    uint32_t r;
    asm("cvt.rn.satfinite.bf16x2.f32 %0, %1, %2;" : "=r"(r) : "f"(hi), "f"(lo));
    return r;
}
__device__ __forceinline__ float bf16_rn_f32(float x) {
    uint32_t r;
    asm("cvt.rn.satfinite.bf16x2.f32 %0, %1, %1;" : "=r"(r) : "f"(x));
    return __uint_as_float(r << 16);
}

#if USE_TC
// ---------------------------------------------------------------------------
// sm_103a-only PTX helpers
// ---------------------------------------------------------------------------
__device__ __forceinline__ uint32_t smem_u32(const void* p) {
    uint32_t a;
    asm("{ .reg .u64 t; cvta.to.shared.u64 t, %1; cvt.u32.u64 %0, t; }"
        : "=r"(a) : "l"(p));
    return a;
}

#define MBAR_INIT(addr, cnt) \
    asm volatile("mbarrier.init.shared.b64 [%0], %1;" :: "r"(addr), "r"(cnt) : "memory")

// local wait, cta-scope acquire
#define MBAR_WAIT(addr, ph) do {                                              \
    uint32_t _m = (addr); uint32_t _p = (ph); uint32_t _done;                 \
    asm volatile("{\n\t.reg .pred p;\n\t"                                     \
        "mbarrier.try_wait.parity.acquire.cta.shared::cta.b64 p, [%1], %2;\n\t" \
        "selp.b32 %0, 1, 0, p;\n\t}"                                          \
        : "=r"(_done) : "r"(_m), "r"(_p) : "memory");                         \
    if (!_done) {                                                             \
        asm volatile("{\n\t.reg .pred P1;\n\t"                                \
            "WL_%=:\n\t"                                                      \
            "mbarrier.try_wait.parity.acquire.cta.shared::cta.b64 P1, [%0], %1, 0x989680;\n\t" \
            "@P1 bra.uni WD_%=;\n\t"                                          \
            "bra.uni WL_%=;\n\t"                                              \
            "WD_%=:\n\t}"                                                     \
            :: "r"(_m), "r"(_p) : "memory");                                  \
    }                                                                         \
} while (0)

// local wait, cluster-scope acquire (protects peer-CTA SMEM reads by cg2 MMA)
#define MBAR_WAIT_CL(addr, ph) do {                                           \
    uint32_t _m = (addr); uint32_t _p = (ph); uint32_t _done;                 \
    asm volatile("{\n\t.reg .pred p;\n\t"                                     \
        "mbarrier.try_wait.parity.acquire.cluster.shared::cta.b64 p, [%1], %2;\n\t" \
        "selp.b32 %0, 1, 0, p;\n\t}"                                          \
        : "=r"(_done) : "r"(_m), "r"(_p) : "memory");                         \
    if (!_done) {                                                             \
        asm volatile("{\n\t.reg .pred P1;\n\t"                                \
            "WL_%=:\n\t"                                                      \
            "mbarrier.try_wait.parity.acquire.cluster.shared::cta.b64 P1, [%0], %1, 0x989680;\n\t" \
            "@P1 bra.uni WD_%=;\n\t"                                          \
            "bra.uni WL_%=;\n\t"                                              \
            "WD_%=:\n\t}"                                                     \
            :: "r"(_m), "r"(_p) : "memory");                                  \
    }                                                                         \
} while (0)

// arrive on cluster-rank-0's mbarrier at the same SMEM offset (mapa)
#define MBAR_ARRIVE_R0(addr) \
    asm volatile("{\n\t.reg .b32 ra;\n\t" \
        "mapa.shared::cluster.u32 ra, %0, %1;\n\t" \
        "mbarrier.arrive.shared::cluster.b64 _, [ra];\n\t}" \
        :: "r"(addr), "r"(0) : "memory")

#define CLUSTER_SYNC() do { \
    asm volatile("barrier.cluster.arrive.aligned;" ::: "memory"); \
    asm volatile("barrier.cluster.wait.aligned;" ::: "memory"); \
} while (0)

#define TC_ALLOC_CG2(sm, n)  asm volatile("tcgen05.alloc.cta_group::2.sync.aligned.shared::cta.b32 [%0], %1;" :: "r"(sm), "r"(n) : "memory")
#define TC_DEALLOC_CG2(t, n) asm volatile("tcgen05.dealloc.cta_group::2.sync.aligned.b32 %0, %1;" :: "r"(t), "r"(n))
#define TC_RELINQ_CG2()      asm volatile("tcgen05.relinquish_alloc_permit.cta_group::2.sync.aligned;")
#define TC_COMMIT_MC2(mb)    asm volatile("tcgen05.commit.cta_group::2.mbarrier::arrive::one.shared::cluster.multicast::cluster.b64 [%0], %1;" :: "r"(mb), "h"((uint16_t)0x3) : "memory")
#define TC_FENCE_AFTER()  asm volatile("tcgen05.fence::after_thread_sync;" ::: "memory")
#define TC_FENCE_BEFORE() asm volatile("tcgen05.fence::before_thread_sync;" ::: "memory")
#define TC_WAIT_LD()      asm volatile("tcgen05.wait::ld.sync.aligned;" ::: "memory")
#define FENCE_ASYNC()     asm volatile("fence.proxy.async.shared::cta;" ::: "memory")

#define CP_ASYNC16(sm, gp) \
    asm volatile("cp.async.cg.shared.global [%0], [%1], 16;" :: "r"(sm), "l"(gp) : "memory")
#define CP_COMMIT() asm volatile("cp.async.commit_group;" ::: "memory")
#define CP_WAIT1()  asm volatile("cp.async.wait_group 1;" ::: "memory")

#define TC_LD_X32(r, a) \
    asm volatile("tcgen05.ld.sync.aligned.32x32b.x32.b32 " \
        "{%0, %1, %2, %3, %4, %5, %6, %7, %8, %9, %10, %11, %12, %13, %14, %15, " \
        " %16, %17, %18, %19, %20, %21, %22, %23, %24, %25, %26, %27, %28, %29, %30, %31}, [%32];" \
        : "=r"((r)[0]), "=r"((r)[1]), "=r"((r)[2]), "=r"((r)[3]), \
          "=r"((r)[4]), "=r"((r)[5]), "=r"((r)[6]), "=r"((r)[7]), \
          "=r"((r)[8]), "=r"((r)[9]), "=r"((r)[10]), "=r"((r)[11]), \
          "=r"((r)[12]), "=r"((r)[13]), "=r"((r)[14]), "=r"((r)[15]), \
          "=r"((r)[16]), "=r"((r)[17]), "=r"((r)[18]), "=r"((r)[19]), \
          "=r"((r)[20]), "=r"((r)[21]), "=r"((r)[22]), "=r"((r)[23]), \
          "=r"((r)[24]), "=r"((r)[25]), "=r"((r)[26]), "=r"((r)[27]), \
          "=r"((r)[28]), "=r"((r)[29]), "=r"((r)[30]), "=r"((r)[31]) \
        : "r"(a))

// cg2 bf16 SS MMA (8-register disable-output-lane vector)
__device__ __forceinline__ void mma_f16_ss_cg2(uint32_t d, uint64_t a, uint64_t b,
                                               uint32_t idesc, uint32_t en) {
    asm volatile("{\n\t.reg .pred p;\n\tsetp.ne.u32 p, %4, 0;\n\t"
        "tcgen05.mma.cta_group::2.kind::f16 [%0], %1, %2, %3, "
        "{%5, %5, %5, %5, %5, %5, %5, %5}, p;\n\t}"
        :: "r"(d), "l"(a), "l"(b), "r"(idesc), "r"(en), "r"(0u) : "memory");
}

__device__ __forceinline__ uint64_t mk_desc(uint32_t addr) {
    const uint64_t base = (uint64_t(2) << 61) | (uint64_t(1) << 46)
                        | (uint64_t(64) << 32) | (uint64_t(1) << 16);
    return base | ((uint64_t)(addr >> 4) & 0x3FFF);
}

__device__ __forceinline__ uint32_t sw128(uint32_t off) {
    return off ^ ((off >> 3) & 0x70);
}
#endif  // USE_TC

// ---------------------------------------------------------------------------
// GEMM (2-CTA clusters, 256M x 512N per cluster):
//   C[z] = (Ahi+Alo)[z] @ (Bhi+Blo)[z]^T.
//   OUTM=0: Cf fp32 (+bias).  OUTM=1: Chi/Clo bf16 pair (+bias).
//   OUTM=2: e=exp(escale*acc) -> pair + row partials.  OUTM=3: acc*rinv[row].
//   Grid: x = M/128 (cluster dim 2 on x), y = N/512, z = batch.
//   M % 256 == 0, N % 512 == 0, K % 64 == 0.
// ---------------------------------------------------------------------------
template <int OUTM, bool HAS_BIAS>
__global__ __launch_bounds__(256, 1) __cluster_dims__(2, 1, 1)
void tc_gemm5(const bf16* __restrict__ Ahi, const bf16* __restrict__ Alo,
              const bf16* __restrict__ Bhi, const bf16* __restrict__ Blo,
              const float* __restrict__ bias,
              float* __restrict__ Cf, bf16* __restrict__ Chi, bf16* __restrict__ Clo,
              const float* __restrict__ rinv, float* __restrict__ Prow, float escale,
              int M, int N, int K,
              long long sA, long long sB, long long sC)
{
    extern __shared__ char smem[];

    Ahi += (long long)blockIdx.z * sA;  Alo += (long long)blockIdx.z * sA;
    Bhi += (long long)blockIdx.z * sB;  Blo += (long long)blockIdx.z * sB;

    const int tid  = threadIdx.x;
    const int rank = blockIdx.x & 1;                  // == cluster_ctarank
    const int m0   = blockIdx.x * 128;                // includes rank offset
    const int n0   = blockIdx.y * BNC;                // 512-wide N tile

#if USE_TC
    const uint32_t sb    = smem_u32(smem);
    const uint32_t tiles = (sb + 64 + 1023) & ~1023u;
    char* tilesg = smem + (tiles - sb);
    const uint32_t mbF[NSTAGE] = { sb,      sb + 8  };   // MMA-done (both CTAs)
    const uint32_t mbR[NSTAGE] = { sb + 16, sb + 24 };   // loads-ready (rank0)
    const uint32_t tptr = sb + 32;

    if (tid < 32) TC_ALLOC_CG2(tptr, 512);
    if (tid == 0) {
        MBAR_INIT(mbF[0], 1); MBAR_INIT(mbF[1], 1);
        MBAR_INIT(mbR[0], 2); MBAR_INIT(mbR[1], 2);
    }
    __syncthreads();
    uint32_t tmem;
    asm volatile("ld.shared.b32 %0, [%1];" : "=r"(tmem) : "r"(tptr));

    // All mbarriers + TMEM alloc visible cluster-wide before any traffic.
    CLUSTER_SYNC();

    const int nk = K / KT;
    int phF[NSTAGE] = { 0, 0 };
    int phR = 0, stR = 0;

    // loader geometry: 2 threads per row, 64B half-rows.
    const int lrow  = tid >> 1;          // 0..127
    const int lhalf = tid & 1;
    const long long aoff  = (long long)(m0 + lrow) * K + lhalf * 32;
    const long long boff0 = (long long)(n0 +       rank * 128 + lrow) * K + lhalf * 32;
    const long long boff1 = (long long)(n0 + 256 + rank * 128 + lrow) * K + lhalf * 32;
    const uint32_t soff   = (uint32_t)(lrow * 128 + lhalf * 64);

    auto load_tile = [&](int tt, uint32_t sbase) {
        const long long kof = (long long)tt * KT;
        const bf16* p0 = Ahi + aoff  + kof;
        const bf16* p1 = Alo + aoff  + kof;
        const bf16* p2 = Bhi + boff0 + kof;
        const bf16* p3 = Blo + boff0 + kof;
        const bf16* p4 = Bhi + boff1 + kof;
        const bf16* p5 = Blo + boff1 + kof;
        #pragma unroll
        for (int j = 0; j < 4; j++) CP_ASYNC16(sbase +         sw128(soff + j * 16), p0 + j * 8);
        #pragma unroll
        for (int j = 0; j < 4; j++) CP_ASYNC16(sbase + 16384 + sw128(soff + j * 16), p1 + j * 8);
        #pragma unroll
        for (int j = 0; j < 4; j++) CP_ASYNC16(sbase + 32768 + sw128(soff + j * 16), p2 + j * 8);
        #pragma unroll
        for (int j = 0; j < 4; j++) CP_ASYNC16(sbase + 49152 + sw128(soff + j * 16), p3 + j * 8);
        #pragma unroll
        for (int j = 0; j < 4; j++) CP_ASYNC16(sbase + 65536 + sw128(soff + j * 16), p4 + j * 8);
        #pragma unroll
        for (int j = 0; j < 4; j++) CP_ASYNC16(sbase + 81920 + sw128(soff + j * 16), p5 + j * 8);
    };

    // prologue: tile 0 -> buf 0
    load_tile(0, tiles);
    CP_COMMIT();

    for (int t = 0; t < nk; t++) {
        const int buf = t & 1;
        const uint32_t sbase = tiles + buf * BUF_BYTES;

        // issue loads for t+1 into the other buffer (gated by MMA-done t-1)
        const int tp = t + 1;
        if (tp < nk) {
            const int nbuf = tp & 1;
            if (tp >= NSTAGE) { MBAR_WAIT(mbF[nbuf], phF[nbuf]); phF[nbuf] ^= 1; }
            load_tile(tp, tiles + nbuf * BUF_BYTES);
        }
        CP_COMMIT();               // keep group count aligned (may be empty)
        CP_WAIT1();                // tile t's loads complete locally
        FENCE_ASYNC();
        __syncthreads();

        // signal: this CTA's stage `buf` ready (arrive on rank0's mbR)
        if (tid == 0) MBAR_ARRIVE_R0(mbR[buf]);

        // rank 0 thread 0: wait both CTAs ready, issue 24 cg2 MMAs (2 halves)
        if (rank == 0 && tid == 0) {
            MBAR_WAIT_CL(mbR[stR], phR);
            if (++stR == NSTAGE) { stR = 0; phR ^= 1; }
            uint64_t ah = mk_desc(sbase);
            uint64_t al = mk_desc(sbase + 16384);
            #pragma unroll
            for (int h = 0; h < 2; h++) {
                uint64_t bh = mk_desc(sbase + 32768 + h * 32768);
                uint64_t bl = mk_desc(sbase + 49152 + h * 32768);
                const uint32_t dt = tmem + h * 256;
                #pragma unroll
                for (int kc = 0; kc < 4; kc++)
                    mma_f16_ss_cg2(dt, ah + kc * 2, bh + kc * 2, IDESC_CG2, (t | kc) != 0);
                #pragma unroll
                for (int kc = 0; kc < 4; kc++)
                    mma_f16_ss_cg2(dt, ah + kc * 2, bl + kc * 2, IDESC_CG2, 1);
                #pragma unroll
                for (int kc = 0; kc < 4; kc++)
                    mma_f16_ss_cg2(dt, al + kc * 2, bh + kc * 2, IDESC_CG2, 1);
            }
            TC_COMMIT_MC2(mbF[buf]);   // arrives at BOTH CTAs' mbF[buf]
        }
    }

    // drain: last commit covers all previously issued MMAs
    {
        const int lastbuf = (nk - 1) & 1;
        MBAR_WAIT(mbF[lastbuf], phF[lastbuf]);
    }
    TC_FENCE_AFTER();

    if (HAS_BIAS) {
        ((float*)tilesg)[tid]       = bias[n0 + tid];
        ((float*)tilesg)[tid + 256] = bias[n0 + tid + 256];
        __syncthreads();
    }

    // epilogue: each CTA reads its 128 TMEM lanes x 512 cols (4 chunks)
    if (tid < 128) {
        const int row = m0 + tid;
        const float* bsm = (const float*)tilesg;
        float rsum = 0.f;
        float rscale = 1.f;
        if (OUTM == 3) rscale = rinv[(long long)blockIdx.z * M + row];

        #pragma unroll
        for (int h = 0; h < 4; h++) {
            uint32_t d[128];
            TC_LD_X32(d +  0, tmem + h * 128 +  0);
            TC_LD_X32(d + 32, tmem + h * 128 + 32);
            TC_LD_X32(d + 64, tmem + h * 128 + 64);
            TC_LD_X32(d + 96, tmem + h * 128 + 96);
            TC_WAIT_LD();
            TC_FENCE_BEFORE();

            if (OUTM == 0) {
                float* cp = Cf + (long long)blockIdx.z * sC
                          + (long long)row * N + n0 + h * 128;
                #pragma unroll
                for (int c = 0; c < 128; c += 4) {
                    float4 o;
                    o.x = __uint_as_float(d[c + 0]);
                    o.y = __uint_as_float(d[c + 1]);
                    o.z = __uint_as_float(d[c + 2]);
                    o.w = __uint_as_float(d[c + 3]);
                    if (HAS_BIAS) {
                        o.x += bsm[h * 128 + c + 0]; o.y += bsm[h * 128 + c + 1];
                        o.z += bsm[h * 128 + c + 2]; o.w += bsm[h * 128 + c + 3];
                    }
                    *reinterpret_cast<float4*>(cp + c) = o;
                }
            } else {
                const long long rb = (long long)blockIdx.z * sC
                                   + (long long)row * N + n0 + h * 128;
                #pragma unroll
                for (int c = 0; c < 128; c += 8) {
                    float v[8];
                    #pragma unroll
                    for (int j = 0; j < 8; j++) {
                        v[j] = __uint_as_float(d[c + j]);
                        if (HAS_BIAS) v[j] += bsm[h * 128 + c + j];
                        if (OUTM == 2) { v[j] = __expf(escale * v[j]); rsum += v[j]; }
                        if (OUTM == 3) v[j] *= rscale;
                    }
                    uint4 hw, lw;
                    hw.x = pack_bf16(v[0], v[1]); hw.y = pack_bf16(v[2], v[3]);
                    hw.z = pack_bf16(v[4], v[5]); hw.w = pack_bf16(v[6], v[7]);
                    float l[8];
                    #pragma unroll
                    for (int j = 0; j < 8; j++) l[j] = v[j] - bf16_rn_f32(v[j]);
                    lw.x = pack_bf16(l[0], l[1]); lw.y = pack_bf16(l[2], l[3]);
                    lw.z = pack_bf16(l[4], l[5]); lw.w = pack_bf16(l[6], l[7]);
                    *reinterpret_cast<uint4*>(Chi + rb + c) = hw;
                    *reinterpret_cast<uint4*>(Clo + rb + c) = lw;
                }
            }
        }
        if (OUTM == 2)
            Prow[((long long)blockIdx.z * M + row) * (N >> 9) + blockIdx.y] = rsum;
    }

    __syncthreads();
    if (tid == 0) {
        asm volatile("mbarrier.inval.shared.b64 [%0];" :: "r"(mbF[0]) : "memory");
        asm volatile("mbarrier.inval.shared.b64 [%0];" :: "r"(mbF[1]) : "memory");
        asm volatile("mbarrier.inval.shared.b64 [%0];" :: "r"(mbR[0]) : "memory");
        asm volatile("mbarrier.inval.shared.b64 [%0];" :: "r"(mbR[1]) : "memory");
    }
    __syncthreads();
    if (tid < 32) { TC_RELINQ_CG2(); TC_DEALLOC_CG2(tmem, 512); }
    CLUSTER_SYNC();

#else
    // ================= SIMT fallback (base target; never selected) =========
    float (*As)[128] = reinterpret_cast<float (*)[128]>(smem);
    float (*Bs)[128] = reinterpret_cast<float (*)[128]>(smem + 4096);

    const int ty = tid >> 4, tx = tid & 15;
    const int aRow = tid >> 1, aCol = (tid & 1) * 4;

    for (int half = 0; half < 4; half++) {
        const int n0h = n0 + half * 128;
        float acc[8][8] = {};
        for (int k0 = 0; k0 < K; k0 += 8) {
            #pragma unroll
            for (int e = 0; e < 4; e++) {
                long long ia = (long long)(m0 + aRow) * K + k0 + aCol + e;
                As[aCol + e][aRow] = __bfloat162float(Ahi[ia]) + __bfloat162float(Alo[ia]);
                long long ib = (long long)(n0h + aRow) * K + k0 + aCol + e;
                Bs[aCol + e][aRow] = __bfloat162float(Bhi[ib]) + __bfloat162float(Blo[ib]);
            }
            __syncthreads();
            #pragma unroll
            for (int kk = 0; kk < 8; kk++) {
                float ra[8], rb[8];
                #pragma unroll
                for (int i = 0; i < 8; i++) ra[i] = As[kk][ty * 8 + i];
                #pragma unroll
                for (int j = 0; j < 8; j++) rb[j] = Bs[kk][tx * 8 + j];
                #pragma unroll
                for (int i = 0; i < 8; i++)
                    #pragma unroll
                    for (int j = 0; j < 8; j++)
                        acc[i][j] = fmaf(ra[i], rb[j], acc[i][j]);
            }
            __syncthreads();
        }
        #pragma unroll
        for (int i = 0; i < 8; i++) {
            const int row = m0 + ty * 8 + i;
            float psum = 0.f;
            #pragma unroll
            for (int j = 0; j < 8; j++) {
                const int col = n0h + tx * 8 + j;
                float val = acc[i][j] + (HAS_BIAS ? bias[col] : 0.f);
                if (OUTM == 2) { val = __expf(escale * val); psum += val; }
                if (OUTM == 3) val *= rinv[(long long)blockIdx.z * M + row];
                long long o = (long long)blockIdx.z * sC + (long long)row * N + col;
                if (OUTM == 0) {
                    Cf[o] = val;
                } else {
                    float hh = bf16_rn_f32(val);
                    Chi[o] = __float2bfloat16(val);
                    Clo[o] = __float2bfloat16(val - hh);
                }
            }
            if (OUTM == 2)
                atomicAdd(&Prow[((long long)blockIdx.z * M + row) * (N >> 9) + blockIdx.y], psum);
        }
        __syncthreads();
    }
#endif
}

// ---------------------------------------------------------------------------
// rowinv: rinv[i] = 1 / sum_t P[i][t]
// ---------------------------------------------------------------------------
__global__ __launch_bounds__(256)
void rowinv_k(const float* __restrict__ P, float* __restrict__ rinv, int ntile)
{
    int i = blockIdx.x * blockDim.x + threadIdx.x;
    if (i >= NB * NSEQ) return;
    const float* p = P + (long long)i * ntile;
    float s = 0.f;
    for (int t = 0; t < ntile; t++) s += p[t];
    rinv[i] = 1.0f / s;
}

// ---------------------------------------------------------------------------
// Elementwise fp32 -> bf16 hi/lo split (n4 = count of float4 groups)
// ---------------------------------------------------------------------------
__global__ __launch_bounds__(256)
void conv_k(const float* __restrict__ in, bf16* __restrict__ oh,
            bf16* __restrict__ ol, long long n4)
{
    long long idx = (long long)blockIdx.x * blockDim.x + threadIdx.x;
    if (idx >= n4) return;
    float4 v = reinterpret_cast<const float4*>(in)[idx];
    uint2 hw, lw;
    hw.x = pack_bf16(v.x, v.y); hw.y = pack_bf16(v.z, v.w);
    lw.x = pack_bf16(v.x - bf16_rn_f32(v.x), v.y - bf16_rn_f32(v.y));
    lw.y = pack_bf16(v.z - bf16_rn_f32(v.z), v.w - bf16_rn_f32(v.w));
    reinterpret_cast<uint2*>(oh)[idx] = hw;
    reinterpret_cast<uint2*>(ol)[idx] = lw;
}

// ---------------------------------------------------------------------------
// 32x32 tiled transpose fp32 -> bf16 hi/lo
// ---------------------------------------------------------------------------
__global__ __launch_bounds__(256)
void transpose_conv_k(const float* __restrict__ in,
                      bf16* __restrict__ oh, bf16* __restrict__ ol,
                      int R, int Cc, long long sIn, long long sOut)
{
    __shared__ float t[32][33];
    in += (long long)blockIdx.z * sIn;
    const long long ob = (long long)blockIdx.z * sOut;
    const int r0 = blockIdx.y * 32, c0 = blockIdx.x * 32;
    const int tx = threadIdx.x & 31, ty = threadIdx.x >> 5;
    #pragma unroll
    for (int i = 0; i < 32; i += 8)
        t[ty + i][tx] = in[(long long)(r0 + ty + i) * Cc + c0 + tx];
    __syncthreads();
    #pragma unroll
    for (int i = 0; i < 32; i += 8) {
        float v = t[tx][ty + i];
        float h = bf16_rn_f32(v);
        long long o = ob + (long long)(c0 + ty + i) * R + r0 + tx;
        oh[o] = __float2bfloat16(v);
        ol[o] = __float2bfloat16(v - h);
    }
}

// ---------------------------------------------------------------------------
extern "C" void kernel_launch(void* const* d_in, const int* in_sizes, int n_in,
                              void* d_out, int out_size)
{
    const float* x  = (const float*)d_in[0];
    const float* Wq = (const float*)d_in[1];
    const float* bq = (const float*)d_in[2];
    const float* Wk = (const float*)d_in[3];
    const float* bk = (const float*)d_in[4];
    const float* Wv = (const float*)d_in[5];
    const float* bv = (const float*)d_in[6];
    const float* Wo = (const float*)d_in[7];
    const float* bo = (const float*)d_in[8];
    float* out = (float*)d_out;

    const int M = NB * NSEQ;
    const float scale = 0.03125f;

    bf16 *xh, *xl, *wth, *wtl, *qh, *ql, *kh, *kl, *vth, *vtl, *ah, *al, *aoh, *aol;
    float *v, *P, *rinv;
    cudaGetSymbolAddress((void**)&xh,  g_xh);  cudaGetSymbolAddress((void**)&xl,  g_xl);
    cudaGetSymbolAddress((void**)&wth, g_wth); cudaGetSymbolAddress((void**)&wtl, g_wtl);
    cudaGetSymbolAddress((void**)&qh,  g_qh);  cudaGetSymbolAddress((void**)&ql,  g_ql);
    cudaGetSymbolAddress((void**)&kh,  g_kh);  cudaGetSymbolAddress((void**)&kl,  g_kl);
    cudaGetSymbolAddress((void**)&v,   g_v);
    cudaGetSymbolAddress((void**)&vth, g_vth); cudaGetSymbolAddress((void**)&vtl, g_vtl);
    cudaGetSymbolAddress((void**)&ah,  g_ah);  cudaGetSymbolAddress((void**)&al,  g_al);
    cudaGetSymbolAddress((void**)&aoh, g_aoh); cudaGetSymbolAddress((void**)&aol, g_aol);
    cudaGetSymbolAddress((void**)&P,   g_P);   cudaGetSymbolAddress((void**)&rinv, g_rinv);

    cudaFuncSetAttribute((const void*)tc_gemm5<0, true>,  cudaFuncAttributeMaxDynamicSharedMemorySize, SMEM_BYTES);
    cudaFuncSetAttribute((const void*)tc_gemm5<1, true>,  cudaFuncAttributeMaxDynamicSharedMemorySize, SMEM_BYTES);
    cudaFuncSetAttribute((const void*)tc_gemm5<2, false>, cudaFuncAttributeMaxDynamicSharedMemorySize, SMEM_BYTES);
    cudaFuncSetAttribute((const void*)tc_gemm5<3, false>, cudaFuncAttributeMaxDynamicSharedMemorySize, SMEM_BYTES);

    const long long qkv = (long long)NSEQ * DIMC;
    const long long ss  = (long long)NSEQ * NSEQ;

    dim3 b256(256);

    // 1) split x -> xh/xl
    conv_k<<<16384, b256>>>(x, xh, xl, 4194304);

    // 2) transpose+split weights
    {
        dim3 g(32, 32, 1);
        transpose_conv_k<<<g, b256>>>(Wq, wth + 0*1048576, wtl + 0*1048576, DIMC, DIMC, 0, 0);
        transpose_conv_k<<<g, b256>>>(Wk, wth + 1*1048576, wtl + 1*1048576, DIMC, DIMC, 0, 0);
        transpose_conv_k<<<g, b256>>>(Wv, wth + 2*1048576, wtl + 2*1048576, DIMC, DIMC, 0, 0);
        transpose_conv_k<<<g, b256>>>(Wo, wth + 3*1048576, wtl + 3*1048576, DIMC, DIMC, 0, 0);
    }

    // 3) q,k (bf16 pair out) and v (fp32 out) projections
    {
        dim3 g(M / 128, DIMC / BNC, 1);
        tc_gemm5<1, true><<<g, b256, SMEM_BYTES>>>(xh, xl, wth + 0*1048576, wtl + 0*1048576,
                                                   bq, nullptr, qh, ql, nullptr, nullptr, 0.f,
                                                   M, DIMC, DIMC, 0, 0, 0);
        tc_gemm5<1, true><<<g, b256, SMEM_BYTES>>>(xh, xl, wth + 1*1048576, wtl + 1*1048576,
                                                   bk, nullptr, kh, kl, nullptr, nullptr, 0.f,
                                                   M, DIMC, DIMC, 0, 0, 0);
        tc_gemm5<0, true><<<g, b256, SMEM_BYTES>>>(xh, xl, wth + 2*1048576, wtl + 2*1048576,
                                                   bv, v, nullptr, nullptr, nullptr, nullptr, 0.f,
                                                   M, DIMC, DIMC, 0, 0, 0);
    }

    // 4) vT split per batch
    {
        dim3 g(DIMC / 32, NSEQ / 32, NB);
        transpose_conv_k<<<g, b256>>>(v, vth, vtl, NSEQ, DIMC, qkv, qkv);
    }

    // 5) e = exp(scale * q@k^T)  -> ah/al (unnormalized) + row partials
    {
        dim3 g(NSEQ / 128, NSEQ / BNC, NB);
        tc_gemm5<2, false><<<g, b256, SMEM_BYTES>>>(qh, ql, kh, kl, nullptr,
                                                    nullptr, ah, al, nullptr, P, scale,
                                                    NSEQ, NSEQ, DIMC, qkv, qkv, ss);
    }

    // 6) rinv = 1/rowsum
    rowinv_k<<<64, b256>>>(P, rinv, NSEQ / BNC);

    // 7) ao = (e @ vT^T) * rinv  (bf16 pair out), K = 4096
    {
        dim3 g(NSEQ / 128, DIMC / BNC, NB);
        tc_gemm5<3, false><<<g, b256, SMEM_BYTES>>>(ah, al, vth, vtl, nullptr,
                                                    nullptr, aoh, aol, rinv, nullptr, 0.f,
                                                    NSEQ, DIMC, NSEQ, ss, qkv, qkv);
    }

    // 8) out = ao @ WoT^T + bo (fp32 out)
    {
        dim3 g(M / 128, DIMC / BNC, 1);
        tc_gemm5<0, true><<<g, b256, SMEM_BYTES>>>(aoh, aol, wth + 3*1048576, wtl + 3*1048576,
                                                   bo, out, nullptr, nullptr, nullptr, nullptr, 0.f,
                                                   M, DIMC, DIMC, 0, 0, 0);
    }
}